// round 12
// baseline (speedup 1.0000x reference)
#include <cuda_runtime.h>
#include <cuda_bf16.h>
#include <cstdint>
#include <cstddef>

#define Bdim 4
#define Tdim 2048
#define Cdim 1024
#define Hdim 16
#define Ddim 64
#define C3   3072
#define Mrows 8192

// bf16 hi/lo scratch
__device__ unsigned short g_x_hi[(size_t)Mrows * Cdim];
__device__ unsigned short g_x_lo[(size_t)Mrows * Cdim];
__device__ unsigned short g_Wa_hi[(size_t)C3 * Cdim];   // transposed [N=3072][K=1024]
__device__ unsigned short g_Wa_lo[(size_t)C3 * Cdim];
__device__ unsigned short g_Wp_hi[(size_t)Cdim * Cdim]; // transposed [N=1024][K=1024]
__device__ unsigned short g_Wp_lo[(size_t)Cdim * Cdim];
__device__ unsigned short g_ah_hi[(size_t)Mrows * Cdim];
__device__ unsigned short g_ah_lo[(size_t)Mrows * Cdim];
__device__ unsigned short g_qkv_hi[(size_t)Mrows * C3];
__device__ unsigned short g_qkv_lo[(size_t)Mrows * C3];

// ---------------------------------------------------------------------------
// PTX helpers (compute_103-safe)
// ---------------------------------------------------------------------------
__device__ __forceinline__ void mma_bf16(float* d,
    uint32_t a0, uint32_t a1, uint32_t a2, uint32_t a3,
    uint32_t b0, uint32_t b1)
{
    asm volatile(
        "mma.sync.aligned.m16n8k16.row.col.f32.bf16.bf16.f32 "
        "{%0,%1,%2,%3}, {%4,%5,%6,%7}, {%8,%9}, {%0,%1,%2,%3};"
        : "+f"(d[0]), "+f"(d[1]), "+f"(d[2]), "+f"(d[3])
        : "r"(a0), "r"(a1), "r"(a2), "r"(a3), "r"(b0), "r"(b1));
}
__device__ __forceinline__ void ldmatrix_x4(uint32_t* r, uint32_t addr) {
    asm volatile("ldmatrix.sync.aligned.m8n8.x4.shared.b16 {%0,%1,%2,%3}, [%4];"
        : "=r"(r[0]), "=r"(r[1]), "=r"(r[2]), "=r"(r[3]) : "r"(addr));
}
__device__ __forceinline__ void ldmatrix_x4_trans(uint32_t* r, uint32_t addr) {
    asm volatile("ldmatrix.sync.aligned.m8n8.x4.trans.shared.b16 {%0,%1,%2,%3}, [%4];"
        : "=r"(r[0]), "=r"(r[1]), "=r"(r[2]), "=r"(r[3]) : "r"(addr));
}
__device__ __forceinline__ uint32_t smem_u32(const void* p) {
    return (uint32_t)__cvta_generic_to_shared(p);
}
__device__ __forceinline__ uint32_t bf16x2_pack(float lo, float hi) {
    uint32_t r;
    asm("cvt.rn.bf16x2.f32 %0, %1, %2;" : "=r"(r) : "f"(hi), "f"(lo));
    return r;
}
__device__ __forceinline__ float bf16_round(float x) {
    __nv_bfloat16 h = __float2bfloat16(x);
    return __bfloat162float(h);
}
__device__ __forceinline__ void cp_async16(void* smem_dst, const void* gsrc) {
    uint32_t sa = smem_u32(smem_dst);
    asm volatile("cp.async.cg.shared.global [%0], [%1], 16;" :: "r"(sa), "l"(gsrc) : "memory");
}
__device__ __forceinline__ void cp_async_commit() {
    asm volatile("cp.async.commit_group;" ::: "memory");
}
template<int N> __device__ __forceinline__ void cp_async_wait() {
    asm volatile("cp.async.wait_group %0;" :: "n"(N) : "memory");
}

// ---------------------------------------------------------------------------
// hi/lo split kernels (inputs only)
// ---------------------------------------------------------------------------
__global__ __launch_bounds__(256) void split_kernel(
    const float* __restrict__ in, unsigned short* __restrict__ hi,
    unsigned short* __restrict__ lo, int n)
{
    int i = blockIdx.x * 256 + threadIdx.x;
    if (i >= n) return;
    float x = in[i];
    __nv_bfloat16 h = __float2bfloat16(x);
    float r = x - __bfloat162float(h);
    __nv_bfloat16 l = __float2bfloat16(r);
    hi[i] = *reinterpret_cast<unsigned short*>(&h);
    lo[i] = *reinterpret_cast<unsigned short*>(&l);
}

__global__ __launch_bounds__(256) void splitT_kernel(
    const float* __restrict__ W, unsigned short* __restrict__ hiT,
    unsigned short* __restrict__ loT, int K, int N)
{
    __shared__ float t[32][33];
    int bn = blockIdx.x * 32;
    int bk = blockIdx.y * 32;
    int tx = threadIdx.x & 31;
    int ty = threadIdx.x >> 5;
#pragma unroll
    for (int i = ty; i < 32; i += 8)
        t[i][tx] = W[(size_t)(bk + i) * N + bn + tx];
    __syncthreads();
#pragma unroll
    for (int i = ty; i < 32; i += 8) {
        float x = t[tx][i];
        __nv_bfloat16 h = __float2bfloat16(x);
        float r = x - __bfloat162float(h);
        __nv_bfloat16 l = __float2bfloat16(r);
        size_t o = (size_t)(bn + i) * K + bk + tx;
        hiT[o] = *reinterpret_cast<unsigned short*>(&h);
        loT[o] = *reinterpret_cast<unsigned short*>(&l);
    }
}

// ---------------------------------------------------------------------------
// GEMM: cp.async double-buffered, one barrier per K-chunk, ldmatrix frags.
// (validated round 10/11; unchanged)
// ---------------------------------------------------------------------------
#define BM 128
#define BN 128
#define BK 32
#define PAD 40
#define GTILE (128 * PAD)
#define GBUF  (4 * GTILE)
#define GEMM_SMEM_BYTES (2 * GBUF * 2)

__global__ __launch_bounds__(256, 2) void gemm_mma_kernel(
    const unsigned short* __restrict__ Ah, const unsigned short* __restrict__ Al,
    const unsigned short* __restrict__ Bh, const unsigned short* __restrict__ Bl,
    const float* __restrict__ bias, float* __restrict__ C,
    unsigned short* __restrict__ OHi, unsigned short* __restrict__ OLo,
    int M, int N, int K)
{
    extern __shared__ unsigned short sm[];

    const int tid = threadIdx.x;
    const int wid = tid >> 5;
    const int lane = tid & 31;
    const int g   = lane >> 2;
    const int tig = lane & 3;
    const int lgrp = lane >> 3;
    const int lrow = lane & 7;
    const int wm  = wid & 3;
    const int wn  = wid >> 2;
    const int bm  = blockIdx.y * BM;
    const int bn  = blockIdx.x * BN;

    float acc[2][8][4];
#pragma unroll
    for (int i = 0; i < 2; i++)
#pragma unroll
        for (int j = 0; j < 8; j++)
#pragma unroll
            for (int v = 0; v < 4; v++) acc[i][j][v] = 0.0f;

    const int lr = tid >> 1;
    const int lh = tid & 1;
    const int nk = K / BK;

    auto load_tile = [&](int s, int buf) {
        const int k0 = s * BK;
        unsigned short* base = sm + buf * GBUF + lr * PAD + lh * 16;
        const size_t aoff = (size_t)(bm + lr) * K + k0 + lh * 16;
        const size_t boff = (size_t)(bn + lr) * K + k0 + lh * 16;
        cp_async16(base + 0 * GTILE,     Ah + aoff);
        cp_async16(base + 0 * GTILE + 8, Ah + aoff + 8);
        cp_async16(base + 1 * GTILE,     Al + aoff);
        cp_async16(base + 1 * GTILE + 8, Al + aoff + 8);
        cp_async16(base + 2 * GTILE,     Bh + boff);
        cp_async16(base + 2 * GTILE + 8, Bh + boff + 8);
        cp_async16(base + 3 * GTILE,     Bl + boff);
        cp_async16(base + 3 * GTILE + 8, Bl + boff + 8);
    };

    load_tile(0, 0);
    cp_async_commit();

    const int a_ro = (lgrp & 1) * 8 + lrow;
    const int a_co = (lgrp >> 1) * 8;
    const int b_ro = (lgrp >> 1) * 8 + lrow;
    const int b_co = (lgrp & 1) * 8;

    for (int s = 0; s < nk; s++) {
        cp_async_wait<0>();
        __syncthreads();
        if (s + 1 < nk) {
            load_tile(s + 1, (s + 1) & 1);
            cp_async_commit();
        }

        const unsigned short* pAh = sm + (s & 1) * GBUF;
        const unsigned short* pAl = pAh + GTILE;
        const unsigned short* pBh = pAl + GTILE;
        const unsigned short* pBl = pBh + GTILE;

#pragma unroll
        for (int ks = 0; ks < 2; ks++) {
            const int kb = ks * 16;
            uint32_t ah[2][4], al[2][4];
#pragma unroll
            for (int mt = 0; mt < 2; mt++) {
                int off = (wm * 32 + mt * 16 + a_ro) * PAD + kb + a_co;
                ldmatrix_x4(ah[mt], smem_u32(pAh + off));
                ldmatrix_x4(al[mt], smem_u32(pAl + off));
            }
#pragma unroll
            for (int p = 0; p < 4; p++) {
                int off = (wn * 64 + p * 16 + b_ro) * PAD + kb + b_co;
                uint32_t bh[4], bl[4];
                ldmatrix_x4(bh, smem_u32(pBh + off));
                ldmatrix_x4(bl, smem_u32(pBl + off));
#pragma unroll
                for (int mt = 0; mt < 2; mt++) {
                    mma_bf16(acc[mt][2*p],   ah[mt][0], ah[mt][1], ah[mt][2], ah[mt][3], bh[0], bh[1]);
                    mma_bf16(acc[mt][2*p],   ah[mt][0], ah[mt][1], ah[mt][2], ah[mt][3], bl[0], bl[1]);
                    mma_bf16(acc[mt][2*p],   al[mt][0], al[mt][1], al[mt][2], al[mt][3], bh[0], bh[1]);
                    mma_bf16(acc[mt][2*p+1], ah[mt][0], ah[mt][1], ah[mt][2], ah[mt][3], bh[2], bh[3]);
                    mma_bf16(acc[mt][2*p+1], ah[mt][0], ah[mt][1], ah[mt][2], ah[mt][3], bl[2], bl[3]);
                    mma_bf16(acc[mt][2*p+1], al[mt][0], al[mt][1], al[mt][2], al[mt][3], bh[2], bh[3]);
                }
            }
        }
    }

    // Epilogue
#pragma unroll
    for (int mt = 0; mt < 2; mt++) {
        int r0 = bm + wm * 32 + mt * 16 + g;
        int r1 = r0 + 8;
#pragma unroll
        for (int nt = 0; nt < 8; nt++) {
            int col = bn + wn * 64 + nt * 8 + tig * 2;
            float b0 = bias[col], b1 = bias[col + 1];
            float v00 = acc[mt][nt][0] + b0, v01 = acc[mt][nt][1] + b1;
            float v10 = acc[mt][nt][2] + b0, v11 = acc[mt][nt][3] + b1;
            if (C) {
                *reinterpret_cast<float2*>(C + (size_t)r0 * N + col) = make_float2(v00, v01);
                *reinterpret_cast<float2*>(C + (size_t)r1 * N + col) = make_float2(v10, v11);
            } else {
                float h00 = bf16_round(v00), h01 = bf16_round(v01);
                float h10 = bf16_round(v10), h11 = bf16_round(v11);
                *reinterpret_cast<uint32_t*>(OHi + (size_t)r0 * N + col) = bf16x2_pack(h00, h01);
                *reinterpret_cast<uint32_t*>(OHi + (size_t)r1 * N + col) = bf16x2_pack(h10, h11);
                *reinterpret_cast<uint32_t*>(OLo + (size_t)r0 * N + col) = bf16x2_pack(v00 - h00, v01 - h01);
                *reinterpret_cast<uint32_t*>(OLo + (size_t)r1 * N + col) = bf16x2_pack(v10 - h10, v11 - h11);
            }
        }
    }
}

// ---------------------------------------------------------------------------
// Tensor-core causal flash attention, 128 q-rows per CTA (8 warps).
// Halves K/V L2 traffic vs the 64-row version (L2-bandwidth-bound kernel).
// K/V stages unchanged: 2 x {Kh,Kl,Vh,Vl} 64xAPAD tiles (73.7 KB).
// Q (128x64 hi+lo) staged through stage-1's 4 tiles, hoisted to registers.
// qt reversed so heaviest CTAs are scheduled first.
// ---------------------------------------------------------------------------
#define APAD 72
#define ATILE (64 * APAD)
#define ABUF  (4 * ATILE)
#define ATTN_SMEM_BYTES (2 * ABUF * 2)

__global__ __launch_bounds__(256) void attn_mma_kernel(
    const unsigned short* __restrict__ qvh, const unsigned short* __restrict__ qvl,
    unsigned short* __restrict__ outHi, unsigned short* __restrict__ outLo)
{
    extern __shared__ unsigned short smem[];

    const int tid = threadIdx.x;
    const int w = tid >> 5, lane = tid & 31;
    const int g = lane >> 2, tig = lane & 3;
    const int lgrp = lane >> 3, lrow = lane & 7;
    const int bh = blockIdx.y, b = bh >> 4, h = bh & 15;
    const int qt = (gridDim.x - 1) - blockIdx.x;   // heavy-first
    const int q0 = qt * 128;
    const int nkb = 2 * qt + 2;

    // K/V stage loader: 256 threads, 2 cp.async16 per tile per thread.
    auto load_kv = [&](int jb, int st) {
        int row = tid >> 2, seg = tid & 3;
        size_t gk = ((size_t)(b * Tdim + jb * 64 + row)) * C3 + Cdim + h * Ddim + seg * 16;
        size_t gv = gk + Cdim;
        unsigned short* base = smem + st * ABUF + row * APAD + seg * 16;
#pragma unroll
        for (int i = 0; i < 2; i++) {
            cp_async16(base + 0 * ATILE + i * 8, qvh + gk + i * 8);
            cp_async16(base + 1 * ATILE + i * 8, qvl + gk + i * 8);
            cp_async16(base + 2 * ATILE + i * 8, qvh + gv + i * 8);
            cp_async16(base + 3 * ATILE + i * 8, qvl + gv + i * 8);
        }
    };

    // Stage Q (128 rows x 64) through stage-1's 4 tiles:
    //   Qh rows 0-63 -> tile0, rows 64-127 -> tile1; Ql -> tiles 2,3.
    {
        int row = tid >> 1, half = tid & 1;
        size_t go = ((size_t)(b * Tdim + q0 + row)) * C3 + h * Ddim + half * 32;
        const uint4* gh = reinterpret_cast<const uint4*>(qvh + go);
        const uint4* gl = reinterpret_cast<const uint4*>(qvl + go);
        unsigned short* qbase = smem + ABUF + (row >> 6) * ATILE + (row & 63) * APAD + half * 32;
        uint4* dh = reinterpret_cast<uint4*>(qbase);
        uint4* dl = reinterpret_cast<uint4*>(qbase + 2 * ATILE);
#pragma unroll
        for (int i = 0; i < 4; i++) { dh[i] = gh[i]; dl[i] = gl[i]; }
    }
    __syncthreads();

    // Hoist Q fragments (warp w -> q rows [w*16, w*16+16))
    uint32_t aqh[4][4], aql[4][4];
    {
        const unsigned short* pQh = smem + ABUF + (w >> 2) * ATILE;
        const unsigned short* pQl = pQh + 2 * ATILE;
        const int ro = ((w & 3) * 16 + (lgrp & 1) * 8 + lrow);   // row within 64-block
#pragma unroll
        for (int kk = 0; kk < 4; kk++) {
            int co = kk * 16 + (lgrp >> 1) * 8;
            ldmatrix_x4(aqh[kk], smem_u32(pQh + ro * APAD + co));
            ldmatrix_x4(aql[kk], smem_u32(pQl + ro * APAD + co));
        }
    }

    load_kv(0, 0);
    cp_async_commit();

    float m0 = -1e30f, m1 = -1e30f, l0 = 0.0f, l1 = 0.0f;
    float O[8][4];
#pragma unroll
    for (int dt = 0; dt < 8; dt++)
#pragma unroll
        for (int v = 0; v < 4; v++) O[dt][v] = 0.0f;

    const int kb_ro = (lgrp >> 1) * 8 + lrow;
    const int kb_co = (lgrp & 1) * 8;
    const int vt_ro = (lgrp & 1) * 8 + lrow;
    const int vt_co = (lgrp >> 1) * 8;
    const int qg0 = q0 + w * 16 + g;      // this lane's first q row
    const int qg1 = qg0 + 8;
    const int wq_max = q0 + w * 16 + 15;  // warp's max q row

    for (int jb = 0; jb < nkb; jb++) {
        cp_async_wait<0>();
        __syncthreads();     // publishes tile jb; fences stage (jb+1)&1 reuse (and Q hoist)
        if (jb + 1 < nkb) {
            load_kv(jb + 1, (jb + 1) & 1);
            cp_async_commit();
        }
        if (jb * 64 > wq_max) continue;   // fully masked for this warp

        const unsigned short* pKh = smem + (jb & 1) * ABUF;
        const unsigned short* pKl = pKh + ATILE;
        const unsigned short* pVh = pKl + ATILE;
        const unsigned short* pVl = pVh + ATILE;

        // S = Q K^T (3 passes)
        float S[8][4];
#pragma unroll
        for (int nt = 0; nt < 8; nt++)
#pragma unroll
            for (int v = 0; v < 4; v++) S[nt][v] = 0.0f;
#pragma unroll
        for (int kk = 0; kk < 4; kk++) {
            const int kb = kk * 16;
#pragma unroll
            for (int p = 0; p < 4; p++) {
                uint32_t kh[4], kl[4];
                int off = (p * 16 + kb_ro) * APAD + kb + kb_co;
                ldmatrix_x4(kh, smem_u32(pKh + off));
                ldmatrix_x4(kl, smem_u32(pKl + off));
                mma_bf16(S[2*p],   aqh[kk][0], aqh[kk][1], aqh[kk][2], aqh[kk][3], kh[0], kh[1]);
                mma_bf16(S[2*p],   aqh[kk][0], aqh[kk][1], aqh[kk][2], aqh[kk][3], kl[0], kl[1]);
                mma_bf16(S[2*p],   aql[kk][0], aql[kk][1], aql[kk][2], aql[kk][3], kh[0], kh[1]);
                mma_bf16(S[2*p+1], aqh[kk][0], aqh[kk][1], aqh[kk][2], aqh[kk][3], kh[2], kh[3]);
                mma_bf16(S[2*p+1], aqh[kk][0], aqh[kk][1], aqh[kk][2], aqh[kk][3], kl[2], kl[3]);
                mma_bf16(S[2*p+1], aql[kk][0], aql[kk][1], aql[kk][2], aql[kk][3], kh[2], kh[3]);
            }
        }

        // Scale + causal mask (global compare; only active near the diagonal)
        const bool need_mask = (jb * 64 + 63) > (q0 + w * 16);
#pragma unroll
        for (int nt = 0; nt < 8; nt++) {
            int jk = jb * 64 + nt * 8 + tig * 2;
            S[nt][0] *= 0.125f; S[nt][1] *= 0.125f;
            S[nt][2] *= 0.125f; S[nt][3] *= 0.125f;
            if (need_mask) {
                if (jk     > qg0) S[nt][0] = -1e30f;
                if (jk + 1 > qg0) S[nt][1] = -1e30f;
                if (jk     > qg1) S[nt][2] = -1e30f;
                if (jk + 1 > qg1) S[nt][3] = -1e30f;
            }
        }

        // Online softmax
        float tm0 = -1e30f, tm1 = -1e30f;
#pragma unroll
        for (int nt = 0; nt < 8; nt++) {
            tm0 = fmaxf(tm0, fmaxf(S[nt][0], S[nt][1]));
            tm1 = fmaxf(tm1, fmaxf(S[nt][2], S[nt][3]));
        }
        tm0 = fmaxf(tm0, __shfl_xor_sync(0xffffffffu, tm0, 1));
        tm0 = fmaxf(tm0, __shfl_xor_sync(0xffffffffu, tm0, 2));
        tm1 = fmaxf(tm1, __shfl_xor_sync(0xffffffffu, tm1, 1));
        tm1 = fmaxf(tm1, __shfl_xor_sync(0xffffffffu, tm1, 2));
        float mn0 = fmaxf(m0, tm0), mn1 = fmaxf(m1, tm1);
        float al0 = __expf(m0 - mn0), al1 = __expf(m1 - mn1);
        m0 = mn0; m1 = mn1;
        l0 *= al0; l1 *= al1;
#pragma unroll
        for (int dt = 0; dt < 8; dt++) {
            O[dt][0] *= al0; O[dt][1] *= al0;
            O[dt][2] *= al1; O[dt][3] *= al1;
        }

        // P hi/lo split; l from (p_hi + p_lo)
        float rs0 = 0.0f, rs1 = 0.0f;
        uint32_t aPh[4][4], aPl[4][4];
#pragma unroll
        for (int nt = 0; nt < 8; nt++) {
            float p0 = __expf(S[nt][0] - m0);
            float p1 = __expf(S[nt][1] - m0);
            float p2 = __expf(S[nt][2] - m1);
            float p3 = __expf(S[nt][3] - m1);
            float p0h = bf16_round(p0), p1h = bf16_round(p1);
            float p2h = bf16_round(p2), p3h = bf16_round(p3);
            float p0l = bf16_round(p0 - p0h), p1l = bf16_round(p1 - p1h);
            float p2l = bf16_round(p2 - p2h), p3l = bf16_round(p3 - p3h);
            rs0 += (p0h + p0l) + (p1h + p1l);
            rs1 += (p2h + p2l) + (p3h + p3l);
            int kk = nt >> 1, hf = (nt & 1) * 2;
            aPh[kk][hf + 0] = bf16x2_pack(p0h, p1h);
            aPh[kk][hf + 1] = bf16x2_pack(p2h, p3h);
            aPl[kk][hf + 0] = bf16x2_pack(p0l, p1l);
            aPl[kk][hf + 1] = bf16x2_pack(p2l, p3l);
        }
        rs0 += __shfl_xor_sync(0xffffffffu, rs0, 1);
        rs0 += __shfl_xor_sync(0xffffffffu, rs0, 2);
        rs1 += __shfl_xor_sync(0xffffffffu, rs1, 1);
        rs1 += __shfl_xor_sync(0xffffffffu, rs1, 2);
        l0 += rs0; l1 += rs1;

        // O += Ph*Vh + Ph*Vl + Pl*Vh; V^T via ldmatrix.trans
#pragma unroll
        for (int kk = 0; kk < 4; kk++) {
            const int kb = kk * 16;
#pragma unroll
            for (int p = 0; p < 4; p++) {
                uint32_t vh[4], vl[4];
                int off = (kb + vt_ro) * APAD + p * 16 + vt_co;
                ldmatrix_x4_trans(vh, smem_u32(pVh + off));
                ldmatrix_x4_trans(vl, smem_u32(pVl + off));
                mma_bf16(O[2*p],   aPh[kk][0], aPh[kk][1], aPh[kk][2], aPh[kk][3], vh[0], vh[1]);
                mma_bf16(O[2*p],   aPh[kk][0], aPh[kk][1], aPh[kk][2], aPh[kk][3], vl[0], vl[1]);
                mma_bf16(O[2*p],   aPl[kk][0], aPl[kk][1], aPl[kk][2], aPl[kk][3], vh[0], vh[1]);
                mma_bf16(O[2*p+1], aPh[kk][0], aPh[kk][1], aPh[kk][2], aPh[kk][3], vh[2], vh[3]);
                mma_bf16(O[2*p+1], aPh[kk][0], aPh[kk][1], aPh[kk][2], aPh[kk][3], vl[2], vl[3]);
                mma_bf16(O[2*p+1], aPl[kk][0], aPl[kk][1], aPl[kk][2], aPl[kk][3], vh[2], vh[3]);
            }
        }
    }

    // Epilogue: write bf16 hi/lo directly (fused split for proj GEMM)
    float inv0 = 1.0f / l0, inv1 = 1.0f / l1;
    int r0 = q0 + w * 16 + g, r1 = r0 + 8;
    size_t o0 = ((size_t)(b * Tdim + r0)) * Cdim + h * Ddim;
    size_t o1 = ((size_t)(b * Tdim + r1)) * Cdim + h * Ddim;
#pragma unroll
    for (int dt = 0; dt < 8; dt++) {
        int d = dt * 8 + tig * 2;
        float v00 = O[dt][0] * inv0, v01 = O[dt][1] * inv0;
        float v10 = O[dt][2] * inv1, v11 = O[dt][3] * inv1;
        float h00 = bf16_round(v00), h01 = bf16_round(v01);
        float h10 = bf16_round(v10), h11 = bf16_round(v11);
        *reinterpret_cast<uint32_t*>(outHi + o0 + d) = bf16x2_pack(h00, h01);
        *reinterpret_cast<uint32_t*>(outHi + o1 + d) = bf16x2_pack(h10, h11);
        *reinterpret_cast<uint32_t*>(outLo + o0 + d) = bf16x2_pack(v00 - h00, v01 - h01);
        *reinterpret_cast<uint32_t*>(outLo + o1 + d) = bf16x2_pack(v10 - h10, v11 - h11);
    }
}

// ---------------------------------------------------------------------------
extern "C" void kernel_launch(void* const* d_in, const int* in_sizes, int n_in,
                              void* d_out, int out_size)
{
    (void)in_sizes; (void)n_in; (void)out_size;
    const float* x      = (const float*)d_in[0];
    const float* W_attn = (const float*)d_in[1];
    const float* b_attn = (const float*)d_in[2];
    const float* W_proj = (const float*)d_in[3];
    const float* b_proj = (const float*)d_in[4];
    float* out = (float*)d_out;

    unsigned short *x_hi, *x_lo, *Wa_hi, *Wa_lo, *Wp_hi, *Wp_lo, *ah_hi, *ah_lo, *qkv_hi, *qkv_lo;
    cudaGetSymbolAddress((void**)&x_hi, g_x_hi);
    cudaGetSymbolAddress((void**)&x_lo, g_x_lo);
    cudaGetSymbolAddress((void**)&Wa_hi, g_Wa_hi);
    cudaGetSymbolAddress((void**)&Wa_lo, g_Wa_lo);
    cudaGetSymbolAddress((void**)&Wp_hi, g_Wp_hi);
    cudaGetSymbolAddress((void**)&Wp_lo, g_Wp_lo);
    cudaGetSymbolAddress((void**)&ah_hi, g_ah_hi);
    cudaGetSymbolAddress((void**)&ah_lo, g_ah_lo);
    cudaGetSymbolAddress((void**)&qkv_hi, g_qkv_hi);
    cudaGetSymbolAddress((void**)&qkv_lo, g_qkv_lo);

    cudaFuncSetAttribute(gemm_mma_kernel,
                         cudaFuncAttributeMaxDynamicSharedMemorySize, GEMM_SMEM_BYTES);
    cudaFuncSetAttribute(attn_mma_kernel,
                         cudaFuncAttributeMaxDynamicSharedMemorySize, ATTN_SMEM_BYTES);

    // Split inputs to bf16 hi/lo (weights transposed to [N,K])
    {
        int n = Mrows * Cdim;
        split_kernel<<<(n + 255) / 256, 256>>>(x, x_hi, x_lo, n);
        splitT_kernel<<<dim3(C3 / 32, Cdim / 32), 256>>>(W_attn, Wa_hi, Wa_lo, Cdim, C3);
        splitT_kernel<<<dim3(Cdim / 32, Cdim / 32), 256>>>(W_proj, Wp_hi, Wp_lo, Cdim, Cdim);
    }
    // 1) QKV = x @ W_attn + b_attn  -> bf16 hi/lo (fused split)
    gemm_mma_kernel<<<dim3(C3 / BN, Mrows / BM), 256, GEMM_SMEM_BYTES>>>(
        x_hi, x_lo, Wa_hi, Wa_lo, b_attn, nullptr, qkv_hi, qkv_lo, Mrows, C3, Cdim);
    // 2) Tensor-core flash attention (128 q-rows/CTA) -> bf16 hi/lo (fused split)
    attn_mma_kernel<<<dim3(Tdim / 128, Bdim * Hdim), 256, ATTN_SMEM_BYTES>>>(
        qkv_hi, qkv_lo, ah_hi, ah_lo);
    // 3) out = att @ W_proj + b_proj  (fp32 epilogue)
    gemm_mma_kernel<<<dim3(Cdim / BN, Mrows / BM), 256, GEMM_SMEM_BYTES>>>(
        ah_hi, ah_lo, Wp_hi, Wp_lo, b_proj, out, nullptr, nullptr, Mrows, Cdim, Cdim);
}

// round 13
// speedup vs baseline: 1.7813x; 1.7813x over previous
#include <cuda_runtime.h>
#include <cuda_bf16.h>
#include <cstdint>
#include <cstddef>

#define Bdim 4
#define Tdim 2048
#define Cdim 1024
#define Hdim 16
#define Ddim 64
#define C3   3072
#define Mrows 8192

// bf16 hi/lo scratch
__device__ unsigned short g_x_hi[(size_t)Mrows * Cdim];
__device__ unsigned short g_x_lo[(size_t)Mrows * Cdim];
__device__ unsigned short g_Wa_hi[(size_t)C3 * Cdim];   // transposed [N=3072][K=1024]
__device__ unsigned short g_Wa_lo[(size_t)C3 * Cdim];
__device__ unsigned short g_Wp_hi[(size_t)Cdim * Cdim]; // transposed [N=1024][K=1024]
__device__ unsigned short g_Wp_lo[(size_t)Cdim * Cdim];
__device__ unsigned short g_ah_hi[(size_t)Mrows * Cdim];
__device__ unsigned short g_ah_lo[(size_t)Mrows * Cdim];
__device__ unsigned short g_qkv_hi[(size_t)Mrows * C3];
__device__ unsigned short g_qkv_lo[(size_t)Mrows * C3];

// ---------------------------------------------------------------------------
// PTX helpers (compute_103-safe)
// ---------------------------------------------------------------------------
__device__ __forceinline__ void mma_bf16(float* d,
    uint32_t a0, uint32_t a1, uint32_t a2, uint32_t a3,
    uint32_t b0, uint32_t b1)
{
    asm volatile(
        "mma.sync.aligned.m16n8k16.row.col.f32.bf16.bf16.f32 "
        "{%0,%1,%2,%3}, {%4,%5,%6,%7}, {%8,%9}, {%0,%1,%2,%3};"
        : "+f"(d[0]), "+f"(d[1]), "+f"(d[2]), "+f"(d[3])
        : "r"(a0), "r"(a1), "r"(a2), "r"(a3), "r"(b0), "r"(b1));
}
__device__ __forceinline__ void ldmatrix_x4(uint32_t* r, uint32_t addr) {
    asm volatile("ldmatrix.sync.aligned.m8n8.x4.shared.b16 {%0,%1,%2,%3}, [%4];"
        : "=r"(r[0]), "=r"(r[1]), "=r"(r[2]), "=r"(r[3]) : "r"(addr));
}
__device__ __forceinline__ void ldmatrix_x4_trans(uint32_t* r, uint32_t addr) {
    asm volatile("ldmatrix.sync.aligned.m8n8.x4.trans.shared.b16 {%0,%1,%2,%3}, [%4];"
        : "=r"(r[0]), "=r"(r[1]), "=r"(r[2]), "=r"(r[3]) : "r"(addr));
}
__device__ __forceinline__ uint32_t smem_u32(const void* p) {
    return (uint32_t)__cvta_generic_to_shared(p);
}
__device__ __forceinline__ uint32_t bf16x2_pack(float lo, float hi) {
    uint32_t r;
    asm("cvt.rn.bf16x2.f32 %0, %1, %2;" : "=r"(r) : "f"(hi), "f"(lo));
    return r;
}
__device__ __forceinline__ float bf16_round(float x) {
    __nv_bfloat16 h = __float2bfloat16(x);
    return __bfloat162float(h);
}
__device__ __forceinline__ void cp_async16(void* smem_dst, const void* gsrc) {
    uint32_t sa = smem_u32(smem_dst);
    asm volatile("cp.async.cg.shared.global [%0], [%1], 16;" :: "r"(sa), "l"(gsrc) : "memory");
}
__device__ __forceinline__ void cp_async_commit() {
    asm volatile("cp.async.commit_group;" ::: "memory");
}
template<int N> __device__ __forceinline__ void cp_async_wait() {
    asm volatile("cp.async.wait_group %0;" :: "n"(N) : "memory");
}

// ---------------------------------------------------------------------------
// Fused input split: one launch does x-split (vectorized), Wa^T split, Wp^T split.
// Block ranges: [0,8192) x | [8192,11264) Wa | [11264,12288) Wp
// ---------------------------------------------------------------------------
#define XBLK 8192
#define WABLK 3072    // (C3/32=96) x (Cdim/32=32)
#define WPBLK 1024    // 32 x 32
#define SPLIT_BLOCKS (XBLK + WABLK + WPBLK)

__device__ __forceinline__ void splitT_tile(
    const float* __restrict__ W, unsigned short* __restrict__ hiT,
    unsigned short* __restrict__ loT, int K, int N, int bn, int bk)
{
    __shared__ float t[32][33];
    int tx = threadIdx.x & 31;
    int ty = threadIdx.x >> 5;
#pragma unroll
    for (int i = ty; i < 32; i += 8)
        t[i][tx] = W[(size_t)(bk + i) * N + bn + tx];
    __syncthreads();
#pragma unroll
    for (int i = ty; i < 32; i += 8) {
        float x = t[tx][i];
        float h = bf16_round(x);
        float l = x - h;
        size_t o = (size_t)(bn + i) * K + bk + tx;
        uint32_t hl = bf16x2_pack(h, l);   // low short = h, high short = l
        hiT[o] = (unsigned short)(hl & 0xFFFF);
        loT[o] = (unsigned short)(hl >> 16);
    }
}

__global__ __launch_bounds__(256) void fused_split_kernel(
    const float* __restrict__ x, unsigned short* __restrict__ x_hi,
    unsigned short* __restrict__ x_lo,
    const float* __restrict__ Wa, unsigned short* __restrict__ Wa_hi,
    unsigned short* __restrict__ Wa_lo,
    const float* __restrict__ Wp, unsigned short* __restrict__ Wp_hi,
    unsigned short* __restrict__ Wp_lo)
{
    int bid = blockIdx.x;
    if (bid < XBLK) {
        // x split, 4 floats per thread
        int i4 = bid * 256 + threadIdx.x;          // float4 index
        float4 v = reinterpret_cast<const float4*>(x)[i4];
        float h0 = bf16_round(v.x), h1 = bf16_round(v.y);
        float h2 = bf16_round(v.z), h3 = bf16_round(v.w);
        uint2 hp, lp;
        hp.x = bf16x2_pack(h0, h1);
        hp.y = bf16x2_pack(h2, h3);
        lp.x = bf16x2_pack(v.x - h0, v.y - h1);
        lp.y = bf16x2_pack(v.z - h2, v.w - h3);
        reinterpret_cast<uint2*>(x_hi)[i4] = hp;
        reinterpret_cast<uint2*>(x_lo)[i4] = lp;
    } else if (bid < XBLK + WABLK) {
        int b2 = bid - XBLK;
        splitT_tile(Wa, Wa_hi, Wa_lo, Cdim, C3, (b2 % 96) * 32, (b2 / 96) * 32);
    } else {
        int b3 = bid - XBLK - WABLK;
        splitT_tile(Wp, Wp_hi, Wp_lo, Cdim, Cdim, (b3 & 31) * 32, (b3 >> 5) * 32);
    }
}

// ---------------------------------------------------------------------------
// GEMM: cp.async double-buffered, ldmatrix frags, accumulator-interleaved MMA
// ordering (distance-4 between same-accumulator HMMAs).
// ---------------------------------------------------------------------------
#define BM 128
#define BN 128
#define BK 32
#define PAD 40
#define GTILE (128 * PAD)
#define GBUF  (4 * GTILE)
#define GEMM_SMEM_BYTES (2 * GBUF * 2)

__global__ __launch_bounds__(256, 2) void gemm_mma_kernel(
    const unsigned short* __restrict__ Ah, const unsigned short* __restrict__ Al,
    const unsigned short* __restrict__ Bh, const unsigned short* __restrict__ Bl,
    const float* __restrict__ bias, float* __restrict__ C,
    unsigned short* __restrict__ OHi, unsigned short* __restrict__ OLo,
    int M, int N, int K)
{
    extern __shared__ unsigned short sm[];

    const int tid = threadIdx.x;
    const int wid = tid >> 5;
    const int lane = tid & 31;
    const int g   = lane >> 2;
    const int tig = lane & 3;
    const int lgrp = lane >> 3;
    const int lrow = lane & 7;
    const int wm  = wid & 3;
    const int wn  = wid >> 2;
    const int bm  = blockIdx.y * BM;
    const int bn  = blockIdx.x * BN;

    float acc[2][8][4];
#pragma unroll
    for (int i = 0; i < 2; i++)
#pragma unroll
        for (int j = 0; j < 8; j++)
#pragma unroll
            for (int v = 0; v < 4; v++) acc[i][j][v] = 0.0f;

    const int lr = tid >> 1;
    const int lh = tid & 1;
    const int nk = K / BK;

    auto load_tile = [&](int s, int buf) {
        const int k0 = s * BK;
        unsigned short* base = sm + buf * GBUF + lr * PAD + lh * 16;
        const size_t aoff = (size_t)(bm + lr) * K + k0 + lh * 16;
        const size_t boff = (size_t)(bn + lr) * K + k0 + lh * 16;
        cp_async16(base + 0 * GTILE,     Ah + aoff);
        cp_async16(base + 0 * GTILE + 8, Ah + aoff + 8);
        cp_async16(base + 1 * GTILE,     Al + aoff);
        cp_async16(base + 1 * GTILE + 8, Al + aoff + 8);
        cp_async16(base + 2 * GTILE,     Bh + boff);
        cp_async16(base + 2 * GTILE + 8, Bh + boff + 8);
        cp_async16(base + 3 * GTILE,     Bl + boff);
        cp_async16(base + 3 * GTILE + 8, Bl + boff + 8);
    };

    load_tile(0, 0);
    cp_async_commit();

    const int a_ro = (lgrp & 1) * 8 + lrow;
    const int a_co = (lgrp >> 1) * 8;
    const int b_ro = (lgrp >> 1) * 8 + lrow;
    const int b_co = (lgrp & 1) * 8;

    for (int s = 0; s < nk; s++) {
        cp_async_wait<0>();
        __syncthreads();
        if (s + 1 < nk) {
            load_tile(s + 1, (s + 1) & 1);
            cp_async_commit();
        }

        const unsigned short* pAh = sm + (s & 1) * GBUF;
        const unsigned short* pAl = pAh + GTILE;
        const unsigned short* pBh = pAl + GTILE;
        const unsigned short* pBl = pBh + GTILE;

#pragma unroll
        for (int ks = 0; ks < 2; ks++) {
            const int kb = ks * 16;
            uint32_t ah[2][4], al[2][4];
#pragma unroll
            for (int mt = 0; mt < 2; mt++) {
                int off = (wm * 32 + mt * 16 + a_ro) * PAD + kb + a_co;
                ldmatrix_x4(ah[mt], smem_u32(pAh + off));
                ldmatrix_x4(al[mt], smem_u32(pAl + off));
            }
#pragma unroll
            for (int p = 0; p < 4; p++) {
                int off = (wn * 64 + p * 16 + b_ro) * PAD + kb + b_co;
                uint32_t bh[4], bl[4];
                ldmatrix_x4(bh, smem_u32(pBh + off));
                ldmatrix_x4(bl, smem_u32(pBl + off));
                // Accumulator-interleaved: same-acc HMMAs are 4 apart
                mma_bf16(acc[0][2*p],   ah[0][0], ah[0][1], ah[0][2], ah[0][3], bh[0], bh[1]);
                mma_bf16(acc[1][2*p],   ah[1][0], ah[1][1], ah[1][2], ah[1][3], bh[0], bh[1]);
                mma_bf16(acc[0][2*p+1], ah[0][0], ah[0][1], ah[0][2], ah[0][3], bh[2], bh[3]);
                mma_bf16(acc[1][2*p+1], ah[1][0], ah[1][1], ah[1][2], ah[1][3], bh[2], bh[3]);
                mma_bf16(acc[0][2*p],   ah[0][0], ah[0][1], ah[0][2], ah[0][3], bl[0], bl[1]);
                mma_bf16(acc[1][2*p],   ah[1][0], ah[1][1], ah[1][2], ah[1][3], bl[0], bl[1]);
                mma_bf16(acc[0][2*p+1], ah[0][0], ah[0][1], ah[0][2], ah[0][3], bl[2], bl[3]);
                mma_bf16(acc[1][2*p+1], ah[1][0], ah[1][1], ah[1][2], ah[1][3], bl[2], bl[3]);
                mma_bf16(acc[0][2*p],   al[0][0], al[0][1], al[0][2], al[0][3], bh[0], bh[1]);
                mma_bf16(acc[1][2*p],   al[1][0], al[1][1], al[1][2], al[1][3], bh[0], bh[1]);
                mma_bf16(acc[0][2*p+1], al[0][0], al[0][1], al[0][2], al[0][3], bh[2], bh[3]);
                mma_bf16(acc[1][2*p+1], al[1][0], al[1][1], al[1][2], al[1][3], bh[2], bh[3]);
            }
        }
    }

    // Epilogue
#pragma unroll
    for (int mt = 0; mt < 2; mt++) {
        int r0 = bm + wm * 32 + mt * 16 + g;
        int r1 = r0 + 8;
#pragma unroll
        for (int nt = 0; nt < 8; nt++) {
            int col = bn + wn * 64 + nt * 8 + tig * 2;
            float b0 = bias[col], b1 = bias[col + 1];
            float v00 = acc[mt][nt][0] + b0, v01 = acc[mt][nt][1] + b1;
            float v10 = acc[mt][nt][2] + b0, v11 = acc[mt][nt][3] + b1;
            if (C) {
                *reinterpret_cast<float2*>(C + (size_t)r0 * N + col) = make_float2(v00, v01);
                *reinterpret_cast<float2*>(C + (size_t)r1 * N + col) = make_float2(v10, v11);
            } else {
                float h00 = bf16_round(v00), h01 = bf16_round(v01);
                float h10 = bf16_round(v10), h11 = bf16_round(v11);
                *reinterpret_cast<uint32_t*>(OHi + (size_t)r0 * N + col) = bf16x2_pack(h00, h01);
                *reinterpret_cast<uint32_t*>(OHi + (size_t)r1 * N + col) = bf16x2_pack(h10, h11);
                *reinterpret_cast<uint32_t*>(OLo + (size_t)r0 * N + col) = bf16x2_pack(v00 - h00, v01 - h01);
                *reinterpret_cast<uint32_t*>(OLo + (size_t)r1 * N + col) = bf16x2_pack(v10 - h10, v11 - h11);
            }
        }
    }
}

// ---------------------------------------------------------------------------
// Tensor-core causal flash attention (round-11 structure: 64 q-rows, 128 thr,
// cp.async double-buffered K/V) + accumulator-interleaved MMA ordering.
// ---------------------------------------------------------------------------
#define APAD 72
#define ATILE (64 * APAD)
#define ABUF  (4 * ATILE)
#define ATTN_SMEM_BYTES (2 * ABUF * 2)

__global__ __launch_bounds__(128) void attn_mma_kernel(
    const unsigned short* __restrict__ qvh, const unsigned short* __restrict__ qvl,
    unsigned short* __restrict__ outHi, unsigned short* __restrict__ outLo)
{
    extern __shared__ unsigned short smem[];

    const int tid = threadIdx.x;
    const int w = tid >> 5, lane = tid & 31;
    const int g = lane >> 2, tig = lane & 3;
    const int lgrp = lane >> 3, lrow = lane & 7;
    const int bh = blockIdx.y, b = bh >> 4, h = bh & 15;
    const int qt = (gridDim.x - 1) - blockIdx.x;   // heavy-first scheduling
    const int q0 = qt * 64;

    auto load_kv = [&](int jb, int st) {
        int row = tid >> 1, half = tid & 1;
        size_t gk = ((size_t)(b * Tdim + jb * 64 + row)) * C3 + Cdim + h * Ddim + half * 32;
        size_t gv = gk + Cdim;
        unsigned short* base = smem + st * ABUF + row * APAD + half * 32;
#pragma unroll
        for (int i = 0; i < 4; i++) {
            cp_async16(base + 0 * ATILE + i * 8, qvh + gk + i * 8);
            cp_async16(base + 1 * ATILE + i * 8, qvl + gk + i * 8);
            cp_async16(base + 2 * ATILE + i * 8, qvh + gv + i * 8);
            cp_async16(base + 3 * ATILE + i * 8, qvl + gv + i * 8);
        }
    };

    // Stage Q through stage-1 K buffers
    {
        int row = tid >> 1, half = tid & 1;
        size_t go = ((size_t)(b * Tdim + q0 + row)) * C3 + h * Ddim + half * 32;
        const uint4* gh = reinterpret_cast<const uint4*>(qvh + go);
        const uint4* gl = reinterpret_cast<const uint4*>(qvl + go);
        uint4* dh = reinterpret_cast<uint4*>(smem + ABUF + 0 * ATILE + row * APAD + half * 32);
        uint4* dl = reinterpret_cast<uint4*>(smem + ABUF + 1 * ATILE + row * APAD + half * 32);
#pragma unroll
        for (int i = 0; i < 4; i++) { dh[i] = gh[i]; dl[i] = gl[i]; }
    }
    __syncthreads();

    // Hoist Q fragments
    uint32_t aqh[4][4], aql[4][4];
    {
        const unsigned short* pQh = smem + ABUF;
        const unsigned short* pQl = pQh + ATILE;
        const int ro = w * 16 + (lgrp & 1) * 8 + lrow;
#pragma unroll
        for (int kk = 0; kk < 4; kk++) {
            int co = kk * 16 + (lgrp >> 1) * 8;
            ldmatrix_x4(aqh[kk], smem_u32(pQh + ro * APAD + co));
            ldmatrix_x4(aql[kk], smem_u32(pQl + ro * APAD + co));
        }
    }

    load_kv(0, 0);
    cp_async_commit();

    float m0 = -1e30f, m1 = -1e30f, l0 = 0.0f, l1 = 0.0f;
    float O[8][4];
#pragma unroll
    for (int dt = 0; dt < 8; dt++)
#pragma unroll
        for (int v = 0; v < 4; v++) O[dt][v] = 0.0f;

    const int kb_ro = (lgrp >> 1) * 8 + lrow;
    const int kb_co = (lgrp & 1) * 8;
    const int vt_ro = (lgrp & 1) * 8 + lrow;
    const int vt_co = (lgrp >> 1) * 8;

    for (int jb = 0; jb <= qt; jb++) {
        cp_async_wait<0>();
        __syncthreads();
        if (jb + 1 <= qt) {
            load_kv(jb + 1, (jb + 1) & 1);
            cp_async_commit();
        }

        const unsigned short* pKh = smem + (jb & 1) * ABUF;
        const unsigned short* pKl = pKh + ATILE;
        const unsigned short* pVh = pKl + ATILE;
        const unsigned short* pVl = pVh + ATILE;

        // S = Q K^T, accumulator-interleaved
        float S[8][4];
#pragma unroll
        for (int nt = 0; nt < 8; nt++)
#pragma unroll
            for (int v = 0; v < 4; v++) S[nt][v] = 0.0f;
#pragma unroll
        for (int kk = 0; kk < 4; kk++) {
            const int kb = kk * 16;
#pragma unroll
            for (int p = 0; p < 4; p++) {
                uint32_t kh[4], kl[4];
                int off = (p * 16 + kb_ro) * APAD + kb + kb_co;
                ldmatrix_x4(kh, smem_u32(pKh + off));
                ldmatrix_x4(kl, smem_u32(pKl + off));
                mma_bf16(S[2*p],   aqh[kk][0], aqh[kk][1], aqh[kk][2], aqh[kk][3], kh[0], kh[1]);
                mma_bf16(S[2*p+1], aqh[kk][0], aqh[kk][1], aqh[kk][2], aqh[kk][3], kh[2], kh[3]);
                mma_bf16(S[2*p],   aqh[kk][0], aqh[kk][1], aqh[kk][2], aqh[kk][3], kl[0], kl[1]);
                mma_bf16(S[2*p+1], aqh[kk][0], aqh[kk][1], aqh[kk][2], aqh[kk][3], kl[2], kl[3]);
                mma_bf16(S[2*p],   aql[kk][0], aql[kk][1], aql[kk][2], aql[kk][3], kh[0], kh[1]);
                mma_bf16(S[2*p+1], aql[kk][0], aql[kk][1], aql[kk][2], aql[kk][3], kh[2], kh[3]);
            }
        }

        // Scale + causal mask (diagonal tile only)
        const int lq0 = w * 16 + g, lq1 = lq0 + 8;
#pragma unroll
        for (int nt = 0; nt < 8; nt++) {
            int lj = nt * 8 + tig * 2;
            S[nt][0] *= 0.125f; S[nt][1] *= 0.125f;
            S[nt][2] *= 0.125f; S[nt][3] *= 0.125f;
            if (jb == qt) {
                if (lj     > lq0) S[nt][0] = -1e30f;
                if (lj + 1 > lq0) S[nt][1] = -1e30f;
                if (lj     > lq1) S[nt][2] = -1e30f;
                if (lj + 1 > lq1) S[nt][3] = -1e30f;
            }
        }

        // Online softmax
        float tm0 = -1e30f, tm1 = -1e30f;
#pragma unroll
        for (int nt = 0; nt < 8; nt++) {
            tm0 = fmaxf(tm0, fmaxf(S[nt][0], S[nt][1]));
            tm1 = fmaxf(tm1, fmaxf(S[nt][2], S[nt][3]));
        }
        tm0 = fmaxf(tm0, __shfl_xor_sync(0xffffffffu, tm0, 1));
        tm0 = fmaxf(tm0, __shfl_xor_sync(0xffffffffu, tm0, 2));
        tm1 = fmaxf(tm1, __shfl_xor_sync(0xffffffffu, tm1, 1));
        tm1 = fmaxf(tm1, __shfl_xor_sync(0xffffffffu, tm1, 2));
        float mn0 = fmaxf(m0, tm0), mn1 = fmaxf(m1, tm1);
        float al0 = __expf(m0 - mn0), al1 = __expf(m1 - mn1);
        m0 = mn0; m1 = mn1;
        l0 *= al0; l1 *= al1;
#pragma unroll
        for (int dt = 0; dt < 8; dt++) {
            O[dt][0] *= al0; O[dt][1] *= al0;
            O[dt][2] *= al1; O[dt][3] *= al1;
        }

        // P hi/lo split; l from (p_hi + p_lo)
        float rs0 = 0.0f, rs1 = 0.0f;
        uint32_t aPh[4][4], aPl[4][4];
#pragma unroll
        for (int nt = 0; nt < 8; nt++) {
            float p0 = __expf(S[nt][0] - m0);
            float p1 = __expf(S[nt][1] - m0);
            float p2 = __expf(S[nt][2] - m1);
            float p3 = __expf(S[nt][3] - m1);
            float p0h = bf16_round(p0), p1h = bf16_round(p1);
            float p2h = bf16_round(p2), p3h = bf16_round(p3);
            float p0l = bf16_round(p0 - p0h), p1l = bf16_round(p1 - p1h);
            float p2l = bf16_round(p2 - p2h), p3l = bf16_round(p3 - p3h);
            rs0 += (p0h + p0l) + (p1h + p1l);
            rs1 += (p2h + p2l) + (p3h + p3l);
            int kk = nt >> 1, hf = (nt & 1) * 2;
            aPh[kk][hf + 0] = bf16x2_pack(p0h, p1h);
            aPh[kk][hf + 1] = bf16x2_pack(p2h, p3h);
            aPl[kk][hf + 0] = bf16x2_pack(p0l, p1l);
            aPl[kk][hf + 1] = bf16x2_pack(p2l, p3l);
        }
        rs0 += __shfl_xor_sync(0xffffffffu, rs0, 1);
        rs0 += __shfl_xor_sync(0xffffffffu, rs0, 2);
        rs1 += __shfl_xor_sync(0xffffffffu, rs1, 1);
        rs1 += __shfl_xor_sync(0xffffffffu, rs1, 2);
        l0 += rs0; l1 += rs1;

        // O += Ph*Vh + Ph*Vl + Pl*Vh, accumulator-interleaved
#pragma unroll
        for (int kk = 0; kk < 4; kk++) {
            const int kb = kk * 16;
#pragma unroll
            for (int p = 0; p < 4; p++) {
                uint32_t vh[4], vl[4];
                int off = (kb + vt_ro) * APAD + p * 16 + vt_co;
                ldmatrix_x4_trans(vh, smem_u32(pVh + off));
                ldmatrix_x4_trans(vl, smem_u32(pVl + off));
                mma_bf16(O[2*p],   aPh[kk][0], aPh[kk][1], aPh[kk][2], aPh[kk][3], vh[0], vh[1]);
                mma_bf16(O[2*p+1], aPh[kk][0], aPh[kk][1], aPh[kk][2], aPh[kk][3], vh[2], vh[3]);
                mma_bf16(O[2*p],   aPh[kk][0], aPh[kk][1], aPh[kk][2], aPh[kk][3], vl[0], vl[1]);
                mma_bf16(O[2*p+1], aPh[kk][0], aPh[kk][1], aPh[kk][2], aPh[kk][3], vl[2], vl[3]);
                mma_bf16(O[2*p],   aPl[kk][0], aPl[kk][1], aPl[kk][2], aPl[kk][3], vh[0], vh[1]);
                mma_bf16(O[2*p+1], aPl[kk][0], aPl[kk][1], aPl[kk][2], aPl[kk][3], vh[2], vh[3]);
            }
        }
    }

    // Epilogue: write bf16 hi/lo directly (fused split for proj GEMM)
    float inv0 = 1.0f / l0, inv1 = 1.0f / l1;
    int r0 = q0 + w * 16 + g, r1 = r0 + 8;
    size_t o0 = ((size_t)(b * Tdim + r0)) * Cdim + h * Ddim;
    size_t o1 = ((size_t)(b * Tdim + r1)) * Cdim + h * Ddim;
#pragma unroll
    for (int dt = 0; dt < 8; dt++) {
        int d = dt * 8 + tig * 2;
        float v00 = O[dt][0] * inv0, v01 = O[dt][1] * inv0;
        float v10 = O[dt][2] * inv1, v11 = O[dt][3] * inv1;
        float h00 = bf16_round(v00), h01 = bf16_round(v01);
        float h10 = bf16_round(v10), h11 = bf16_round(v11);
        *reinterpret_cast<uint32_t*>(outHi + o0 + d) = bf16x2_pack(h00, h01);
        *reinterpret_cast<uint32_t*>(outHi + o1 + d) = bf16x2_pack(h10, h11);
        *reinterpret_cast<uint32_t*>(outLo + o0 + d) = bf16x2_pack(v00 - h00, v01 - h01);
        *reinterpret_cast<uint32_t*>(outLo + o1 + d) = bf16x2_pack(v10 - h10, v11 - h11);
    }
}

// ---------------------------------------------------------------------------
extern "C" void kernel_launch(void* const* d_in, const int* in_sizes, int n_in,
                              void* d_out, int out_size)
{
    (void)in_sizes; (void)n_in; (void)out_size;
    const float* x      = (const float*)d_in[0];
    const float* W_attn = (const float*)d_in[1];
    const float* b_attn = (const float*)d_in[2];
    const float* W_proj = (const float*)d_in[3];
    const float* b_proj = (const float*)d_in[4];
    float* out = (float*)d_out;

    unsigned short *x_hi, *x_lo, *Wa_hi, *Wa_lo, *Wp_hi, *Wp_lo, *ah_hi, *ah_lo, *qkv_hi, *qkv_lo;
    cudaGetSymbolAddress((void**)&x_hi, g_x_hi);
    cudaGetSymbolAddress((void**)&x_lo, g_x_lo);
    cudaGetSymbolAddress((void**)&Wa_hi, g_Wa_hi);
    cudaGetSymbolAddress((void**)&Wa_lo, g_Wa_lo);
    cudaGetSymbolAddress((void**)&Wp_hi, g_Wp_hi);
    cudaGetSymbolAddress((void**)&Wp_lo, g_Wp_lo);
    cudaGetSymbolAddress((void**)&ah_hi, g_ah_hi);
    cudaGetSymbolAddress((void**)&ah_lo, g_ah_lo);
    cudaGetSymbolAddress((void**)&qkv_hi, g_qkv_hi);
    cudaGetSymbolAddress((void**)&qkv_lo, g_qkv_lo);

    cudaFuncSetAttribute(gemm_mma_kernel,
                         cudaFuncAttributeMaxDynamicSharedMemorySize, GEMM_SMEM_BYTES);
    cudaFuncSetAttribute(attn_mma_kernel,
                         cudaFuncAttributeMaxDynamicSharedMemorySize, ATTN_SMEM_BYTES);

    // 0) Fused input splits (x, Wa^T, Wp^T) in one launch
    fused_split_kernel<<<SPLIT_BLOCKS, 256>>>(
        x, x_hi, x_lo, W_attn, Wa_hi, Wa_lo, W_proj, Wp_hi, Wp_lo);
    // 1) QKV = x @ W_attn + b_attn  -> bf16 hi/lo (fused split)
    gemm_mma_kernel<<<dim3(C3 / BN, Mrows / BM), 256, GEMM_SMEM_BYTES>>>(
        x_hi, x_lo, Wa_hi, Wa_lo, b_attn, nullptr, qkv_hi, qkv_lo, Mrows, C3, Cdim);
    // 2) Tensor-core flash attention -> bf16 hi/lo (fused split)
    attn_mma_kernel<<<dim3(Tdim / 64, Bdim * Hdim), 128, ATTN_SMEM_BYTES>>>(
        qkv_hi, qkv_lo, ah_hi, ah_lo);
    // 3) out = att @ W_proj + b_proj  (fp32 epilogue)
    gemm_mma_kernel<<<dim3(Cdim / BN, Mrows / BM), 256, GEMM_SMEM_BYTES>>>(
        ah_hi, ah_lo, Wp_hi, Wp_lo, b_proj, out, nullptr, nullptr, Mrows, Cdim, Cdim);
}

// round 15
// speedup vs baseline: 1.8597x; 1.0440x over previous
#include <cuda_runtime.h>
#include <cuda_bf16.h>
#include <cstdint>
#include <cstddef>

#define Bdim 4
#define Tdim 2048
#define Cdim 1024
#define Hdim 16
#define Ddim 64
#define C3   3072
#define Mrows 8192

// bf16 hi/lo scratch
__device__ unsigned short g_x_hi[(size_t)Mrows * Cdim];
__device__ unsigned short g_x_lo[(size_t)Mrows * Cdim];
__device__ unsigned short g_Wa_hi[(size_t)C3 * Cdim];   // transposed [N=3072][K=1024]
__device__ unsigned short g_Wa_lo[(size_t)C3 * Cdim];
__device__ unsigned short g_Wp_hi[(size_t)Cdim * Cdim]; // transposed [N=1024][K=1024]
__device__ unsigned short g_Wp_lo[(size_t)Cdim * Cdim];
__device__ unsigned short g_ah_hi[(size_t)Mrows * Cdim];
__device__ unsigned short g_ah_lo[(size_t)Mrows * Cdim];
__device__ unsigned short g_qkv_hi[(size_t)Mrows * C3];
__device__ unsigned short g_qkv_lo[(size_t)Mrows * C3];

// ---------------------------------------------------------------------------
// PTX helpers (compute_103-safe)
// ---------------------------------------------------------------------------
__device__ __forceinline__ void mma_bf16(float* d,
    uint32_t a0, uint32_t a1, uint32_t a2, uint32_t a3,
    uint32_t b0, uint32_t b1)
{
    asm volatile(
        "mma.sync.aligned.m16n8k16.row.col.f32.bf16.bf16.f32 "
        "{%0,%1,%2,%3}, {%4,%5,%6,%7}, {%8,%9}, {%0,%1,%2,%3};"
        : "+f"(d[0]), "+f"(d[1]), "+f"(d[2]), "+f"(d[3])
        : "r"(a0), "r"(a1), "r"(a2), "r"(a3), "r"(b0), "r"(b1));
}
__device__ __forceinline__ void ldmatrix_x4(uint32_t* r, uint32_t addr) {
    asm volatile("ldmatrix.sync.aligned.m8n8.x4.shared.b16 {%0,%1,%2,%3}, [%4];"
        : "=r"(r[0]), "=r"(r[1]), "=r"(r[2]), "=r"(r[3]) : "r"(addr));
}
__device__ __forceinline__ void ldmatrix_x4_trans(uint32_t* r, uint32_t addr) {
    asm volatile("ldmatrix.sync.aligned.m8n8.x4.trans.shared.b16 {%0,%1,%2,%3}, [%4];"
        : "=r"(r[0]), "=r"(r[1]), "=r"(r[2]), "=r"(r[3]) : "r"(addr));
}
__device__ __forceinline__ uint32_t smem_u32(const void* p) {
    return (uint32_t)__cvta_generic_to_shared(p);
}
__device__ __forceinline__ uint32_t bf16x2_pack(float lo, float hi) {
    uint32_t r;
    asm("cvt.rn.bf16x2.f32 %0, %1, %2;" : "=r"(r) : "f"(hi), "f"(lo));
    return r;
}
__device__ __forceinline__ float bf16_round(float x) {
    __nv_bfloat16 h = __float2bfloat16(x);
    return __bfloat162float(h);
}
__device__ __forceinline__ float ex2(float x) {
    float r;
    asm("ex2.approx.f32 %0, %1;" : "=f"(r) : "f"(x));
    return r;
}
__device__ __forceinline__ void cp_async16(void* smem_dst, const void* gsrc) {
    uint32_t sa = smem_u32(smem_dst);
    asm volatile("cp.async.cg.shared.global [%0], [%1], 16;" :: "r"(sa), "l"(gsrc) : "memory");
}
__device__ __forceinline__ void cp_async_commit() {
    asm volatile("cp.async.commit_group;" ::: "memory");
}
template<int N> __device__ __forceinline__ void cp_async_wait() {
    asm volatile("cp.async.wait_group %0;" :: "n"(N) : "memory");
}

// S pre-scaled by 0.125 * log2(e) via the QKV epilogue Q-column scale.
#define QSCALE 0.18033688011112042f

// ---------------------------------------------------------------------------
// Fused input split (one launch: x vectorized + Wa^T + Wp^T)
// ---------------------------------------------------------------------------
#define XBLK 8192
#define WABLK 3072
#define WPBLK 1024
#define SPLIT_BLOCKS (XBLK + WABLK + WPBLK)

__device__ __forceinline__ void splitT_tile(
    const float* __restrict__ W, unsigned short* __restrict__ hiT,
    unsigned short* __restrict__ loT, int K, int N, int bn, int bk)
{
    __shared__ float t[32][33];
    int tx = threadIdx.x & 31;
    int ty = threadIdx.x >> 5;
#pragma unroll
    for (int i = ty; i < 32; i += 8)
        t[i][tx] = W[(size_t)(bk + i) * N + bn + tx];
    __syncthreads();
#pragma unroll
    for (int i = ty; i < 32; i += 8) {
        float x = t[tx][i];
        float h = bf16_round(x);
        float l = x - h;
        size_t o = (size_t)(bn + i) * K + bk + tx;
        uint32_t hl = bf16x2_pack(h, l);
        hiT[o] = (unsigned short)(hl & 0xFFFF);
        loT[o] = (unsigned short)(hl >> 16);
    }
}

__global__ __launch_bounds__(256) void fused_split_kernel(
    const float* __restrict__ x, unsigned short* __restrict__ x_hi,
    unsigned short* __restrict__ x_lo,
    const float* __restrict__ Wa, unsigned short* __restrict__ Wa_hi,
    unsigned short* __restrict__ Wa_lo,
    const float* __restrict__ Wp, unsigned short* __restrict__ Wp_hi,
    unsigned short* __restrict__ Wp_lo)
{
    int bid = blockIdx.x;
    if (bid < XBLK) {
        int i4 = bid * 256 + threadIdx.x;
        float4 v = reinterpret_cast<const float4*>(x)[i4];
        float h0 = bf16_round(v.x), h1 = bf16_round(v.y);
        float h2 = bf16_round(v.z), h3 = bf16_round(v.w);
        uint2 hp, lp;
        hp.x = bf16x2_pack(h0, h1);
        hp.y = bf16x2_pack(h2, h3);
        lp.x = bf16x2_pack(v.x - h0, v.y - h1);
        lp.y = bf16x2_pack(v.z - h2, v.w - h3);
        reinterpret_cast<uint2*>(x_hi)[i4] = hp;
        reinterpret_cast<uint2*>(x_lo)[i4] = lp;
    } else if (bid < XBLK + WABLK) {
        int b2 = bid - XBLK;
        splitT_tile(Wa, Wa_hi, Wa_lo, Cdim, C3, (b2 % 96) * 32, (b2 / 96) * 32);
    } else {
        int b3 = bid - XBLK - WABLK;
        splitT_tile(Wp, Wp_hi, Wp_lo, Cdim, Cdim, (b3 & 31) * 32, (b3 >> 5) * 32);
    }
}

// ---------------------------------------------------------------------------
// GEMM: 2-stage cp.async pipeline, PAD=40 (16B-aligned rows: 80 bytes),
// ldmatrix frags, accumulator-interleaved MMAs. (round-13 validated)
// ---------------------------------------------------------------------------
#define BM 128
#define BN 128
#define BK 32
#define PAD 40
#define GTILE (128 * PAD)
#define GBUF  (4 * GTILE)
#define GEMM_SMEM_BYTES (2 * GBUF * 2)

__global__ __launch_bounds__(256, 2) void gemm_mma_kernel(
    const unsigned short* __restrict__ Ah, const unsigned short* __restrict__ Al,
    const unsigned short* __restrict__ Bh, const unsigned short* __restrict__ Bl,
    const float* __restrict__ bias, float* __restrict__ C,
    unsigned short* __restrict__ OHi, unsigned short* __restrict__ OLo,
    int M, int N, int K, int qcols, float qscale)
{
    extern __shared__ unsigned short sm[];

    const int tid = threadIdx.x;
    const int wid = tid >> 5;
    const int lane = tid & 31;
    const int g   = lane >> 2;
    const int tig = lane & 3;
    const int lgrp = lane >> 3;
    const int lrow = lane & 7;
    const int wm  = wid & 3;
    const int wn  = wid >> 2;
    const int bm  = blockIdx.y * BM;
    const int bn  = blockIdx.x * BN;

    float acc[2][8][4];
#pragma unroll
    for (int i = 0; i < 2; i++)
#pragma unroll
        for (int j = 0; j < 8; j++)
#pragma unroll
            for (int v = 0; v < 4; v++) acc[i][j][v] = 0.0f;

    const int lr = tid >> 1;
    const int lh = tid & 1;
    const int nk = K / BK;

    auto load_tile = [&](int s, int buf) {
        const int k0 = s * BK;
        unsigned short* base = sm + buf * GBUF + lr * PAD + lh * 16;
        const size_t aoff = (size_t)(bm + lr) * K + k0 + lh * 16;
        const size_t boff = (size_t)(bn + lr) * K + k0 + lh * 16;
        cp_async16(base + 0 * GTILE,     Ah + aoff);
        cp_async16(base + 0 * GTILE + 8, Ah + aoff + 8);
        cp_async16(base + 1 * GTILE,     Al + aoff);
        cp_async16(base + 1 * GTILE + 8, Al + aoff + 8);
        cp_async16(base + 2 * GTILE,     Bh + boff);
        cp_async16(base + 2 * GTILE + 8, Bh + boff + 8);
        cp_async16(base + 3 * GTILE,     Bl + boff);
        cp_async16(base + 3 * GTILE + 8, Bl + boff + 8);
    };

    load_tile(0, 0);
    cp_async_commit();

    const int a_ro = (lgrp & 1) * 8 + lrow;
    const int a_co = (lgrp >> 1) * 8;
    const int b_ro = (lgrp >> 1) * 8 + lrow;
    const int b_co = (lgrp & 1) * 8;

    for (int s = 0; s < nk; s++) {
        cp_async_wait<0>();
        __syncthreads();
        if (s + 1 < nk) {
            load_tile(s + 1, (s + 1) & 1);
            cp_async_commit();
        }

        const unsigned short* pAh = sm + (s & 1) * GBUF;
        const unsigned short* pAl = pAh + GTILE;
        const unsigned short* pBh = pAl + GTILE;
        const unsigned short* pBl = pBh + GTILE;

#pragma unroll
        for (int ks = 0; ks < 2; ks++) {
            const int kb = ks * 16;
            uint32_t ah[2][4], al[2][4];
#pragma unroll
            for (int mt = 0; mt < 2; mt++) {
                int off = (wm * 32 + mt * 16 + a_ro) * PAD + kb + a_co;
                ldmatrix_x4(ah[mt], smem_u32(pAh + off));
                ldmatrix_x4(al[mt], smem_u32(pAl + off));
            }
#pragma unroll
            for (int p = 0; p < 4; p++) {
                int off = (wn * 64 + p * 16 + b_ro) * PAD + kb + b_co;
                uint32_t bh[4], bl[4];
                ldmatrix_x4(bh, smem_u32(pBh + off));
                ldmatrix_x4(bl, smem_u32(pBl + off));
                mma_bf16(acc[0][2*p],   ah[0][0], ah[0][1], ah[0][2], ah[0][3], bh[0], bh[1]);
                mma_bf16(acc[1][2*p],   ah[1][0], ah[1][1], ah[1][2], ah[1][3], bh[0], bh[1]);
                mma_bf16(acc[0][2*p+1], ah[0][0], ah[0][1], ah[0][2], ah[0][3], bh[2], bh[3]);
                mma_bf16(acc[1][2*p+1], ah[1][0], ah[1][1], ah[1][2], ah[1][3], bh[2], bh[3]);
                mma_bf16(acc[0][2*p],   ah[0][0], ah[0][1], ah[0][2], ah[0][3], bl[0], bl[1]);
                mma_bf16(acc[1][2*p],   ah[1][0], ah[1][1], ah[1][2], ah[1][3], bl[0], bl[1]);
                mma_bf16(acc[0][2*p+1], ah[0][0], ah[0][1], ah[0][2], ah[0][3], bl[2], bl[3]);
                mma_bf16(acc[1][2*p+1], ah[1][0], ah[1][1], ah[1][2], ah[1][3], bl[2], bl[3]);
                mma_bf16(acc[0][2*p],   al[0][0], al[0][1], al[0][2], al[0][3], bh[0], bh[1]);
                mma_bf16(acc[1][2*p],   al[1][0], al[1][1], al[1][2], al[1][3], bh[0], bh[1]);
                mma_bf16(acc[0][2*p+1], al[0][0], al[0][1], al[0][2], al[0][3], bh[2], bh[3]);
                mma_bf16(acc[1][2*p+1], al[1][0], al[1][1], al[1][2], al[1][3], bh[2], bh[3]);
            }
        }
    }

    // Epilogue
#pragma unroll
    for (int mt = 0; mt < 2; mt++) {
        int r0 = bm + wm * 32 + mt * 16 + g;
        int r1 = r0 + 8;
#pragma unroll
        for (int nt = 0; nt < 8; nt++) {
            int col = bn + wn * 64 + nt * 8 + tig * 2;
            float b0 = bias[col], b1 = bias[col + 1];
            float v00 = acc[mt][nt][0] + b0, v01 = acc[mt][nt][1] + b1;
            float v10 = acc[mt][nt][2] + b0, v11 = acc[mt][nt][3] + b1;
            if (C) {
                *reinterpret_cast<float2*>(C + (size_t)r0 * N + col) = make_float2(v00, v01);
                *reinterpret_cast<float2*>(C + (size_t)r1 * N + col) = make_float2(v10, v11);
            } else {
                float sc = (col < qcols) ? qscale : 1.0f;   // pre-scale Q columns
                v00 *= sc; v01 *= sc; v10 *= sc; v11 *= sc;
                uint32_t h0 = bf16x2_pack(v00, v01);
                uint32_t h1 = bf16x2_pack(v10, v11);
                float h00 = __uint_as_float(h0 << 16);
                float h01 = __uint_as_float(h0 & 0xFFFF0000u);
                float h10 = __uint_as_float(h1 << 16);
                float h11 = __uint_as_float(h1 & 0xFFFF0000u);
                *reinterpret_cast<uint32_t*>(OHi + (size_t)r0 * N + col) = h0;
                *reinterpret_cast<uint32_t*>(OHi + (size_t)r1 * N + col) = h1;
                *reinterpret_cast<uint32_t*>(OLo + (size_t)r0 * N + col) = bf16x2_pack(v00 - h00, v01 - h01);
                *reinterpret_cast<uint32_t*>(OLo + (size_t)r1 * N + col) = bf16x2_pack(v10 - h10, v11 - h11);
            }
        }
    }
}

// ---------------------------------------------------------------------------
// Tensor-core causal flash attention (64 q-rows, 128 thr, cp.async 2-stage).
// exp2-domain softmax (Q pre-scaled); P/output splits via pack-then-bit-unpack.
// ---------------------------------------------------------------------------
#define APAD 72
#define ATILE (64 * APAD)
#define ABUF  (4 * ATILE)
#define ATTN_SMEM_BYTES (2 * ABUF * 2)

__global__ __launch_bounds__(128) void attn_mma_kernel(
    const unsigned short* __restrict__ qvh, const unsigned short* __restrict__ qvl,
    unsigned short* __restrict__ outHi, unsigned short* __restrict__ outLo)
{
    extern __shared__ unsigned short smem[];

    const int tid = threadIdx.x;
    const int w = tid >> 5, lane = tid & 31;
    const int g = lane >> 2, tig = lane & 3;
    const int lgrp = lane >> 3, lrow = lane & 7;
    const int bh = blockIdx.y, b = bh >> 4, h = bh & 15;
    const int qt = (gridDim.x - 1) - blockIdx.x;   // heavy-first
    const int q0 = qt * 64;

    auto load_kv = [&](int jb, int st) {
        int row = tid >> 1, half = tid & 1;
        size_t gk = ((size_t)(b * Tdim + jb * 64 + row)) * C3 + Cdim + h * Ddim + half * 32;
        size_t gv = gk + Cdim;
        unsigned short* base = smem + st * ABUF + row * APAD + half * 32;
#pragma unroll
        for (int i = 0; i < 4; i++) {
            cp_async16(base + 0 * ATILE + i * 8, qvh + gk + i * 8);
            cp_async16(base + 1 * ATILE + i * 8, qvl + gk + i * 8);
            cp_async16(base + 2 * ATILE + i * 8, qvh + gv + i * 8);
            cp_async16(base + 3 * ATILE + i * 8, qvl + gv + i * 8);
        }
    };

    // Stage Q through stage-1 K buffers
    {
        int row = tid >> 1, half = tid & 1;
        size_t go = ((size_t)(b * Tdim + q0 + row)) * C3 + h * Ddim + half * 32;
        const uint4* gh = reinterpret_cast<const uint4*>(qvh + go);
        const uint4* gl = reinterpret_cast<const uint4*>(qvl + go);
        uint4* dh = reinterpret_cast<uint4*>(smem + ABUF + 0 * ATILE + row * APAD + half * 32);
        uint4* dl = reinterpret_cast<uint4*>(smem + ABUF + 1 * ATILE + row * APAD + half * 32);
#pragma unroll
        for (int i = 0; i < 4; i++) { dh[i] = gh[i]; dl[i] = gl[i]; }
    }
    __syncthreads();

    // Hoist Q fragments
    uint32_t aqh[4][4], aql[4][4];
    {
        const unsigned short* pQh = smem + ABUF;
        const unsigned short* pQl = pQh + ATILE;
        const int ro = w * 16 + (lgrp & 1) * 8 + lrow;
#pragma unroll
        for (int kk = 0; kk < 4; kk++) {
            int co = kk * 16 + (lgrp >> 1) * 8;
            ldmatrix_x4(aqh[kk], smem_u32(pQh + ro * APAD + co));
            ldmatrix_x4(aql[kk], smem_u32(pQl + ro * APAD + co));
        }
    }

    load_kv(0, 0);
    cp_async_commit();

    float m0 = -1e30f, m1 = -1e30f, l0 = 0.0f, l1 = 0.0f;
    float O[8][4];
#pragma unroll
    for (int dt = 0; dt < 8; dt++)
#pragma unroll
        for (int v = 0; v < 4; v++) O[dt][v] = 0.0f;

    const int kb_ro = (lgrp >> 1) * 8 + lrow;
    const int kb_co = (lgrp & 1) * 8;
    const int vt_ro = (lgrp & 1) * 8 + lrow;
    const int vt_co = (lgrp >> 1) * 8;

    for (int jb = 0; jb <= qt; jb++) {
        cp_async_wait<0>();
        __syncthreads();
        if (jb + 1 <= qt) {
            load_kv(jb + 1, (jb + 1) & 1);
            cp_async_commit();
        }

        const unsigned short* pKh = smem + (jb & 1) * ABUF;
        const unsigned short* pKl = pKh + ATILE;
        const unsigned short* pVh = pKl + ATILE;
        const unsigned short* pVl = pVh + ATILE;

        // S = Q K^T (pre-scaled to exp2 domain)
        float S[8][4];
#pragma unroll
        for (int nt = 0; nt < 8; nt++)
#pragma unroll
            for (int v = 0; v < 4; v++) S[nt][v] = 0.0f;
#pragma unroll
        for (int kk = 0; kk < 4; kk++) {
            const int kb = kk * 16;
#pragma unroll
            for (int p = 0; p < 4; p++) {
                uint32_t kh[4], kl[4];
                int off = (p * 16 + kb_ro) * APAD + kb + kb_co;
                ldmatrix_x4(kh, smem_u32(pKh + off));
                ldmatrix_x4(kl, smem_u32(pKl + off));
                mma_bf16(S[2*p],   aqh[kk][0], aqh[kk][1], aqh[kk][2], aqh[kk][3], kh[0], kh[1]);
                mma_bf16(S[2*p+1], aqh[kk][0], aqh[kk][1], aqh[kk][2], aqh[kk][3], kh[2], kh[3]);
                mma_bf16(S[2*p],   aqh[kk][0], aqh[kk][1], aqh[kk][2], aqh[kk][3], kl[0], kl[1]);
                mma_bf16(S[2*p+1], aqh[kk][0], aqh[kk][1], aqh[kk][2], aqh[kk][3], kl[2], kl[3]);
                mma_bf16(S[2*p],   aql[kk][0], aql[kk][1], aql[kk][2], aql[kk][3], kh[0], kh[1]);
                mma_bf16(S[2*p+1], aql[kk][0], aql[kk][1], aql[kk][2], aql[kk][3], kh[2], kh[3]);
            }
        }

        // Causal mask (diagonal tile only)
        if (jb == qt) {
            const int lq0 = w * 16 + g, lq1 = lq0 + 8;
#pragma unroll
            for (int nt = 0; nt < 8; nt++) {
                int lj = nt * 8 + tig * 2;
                if (lj     > lq0) S[nt][0] = -1e30f;
                if (lj + 1 > lq0) S[nt][1] = -1e30f;
                if (lj     > lq1) S[nt][2] = -1e30f;
                if (lj + 1 > lq1) S[nt][3] = -1e30f;
            }
        }

        // Online softmax (exp2 domain)
        float tm0 = -1e30f, tm1 = -1e30f;
#pragma unroll
        for (int nt = 0; nt < 8; nt++) {
            tm0 = fmaxf(tm0, fmaxf(S[nt][0], S[nt][1]));
            tm1 = fmaxf(tm1, fmaxf(S[nt][2], S[nt][3]));
        }
        tm0 = fmaxf(tm0, __shfl_xor_sync(0xffffffffu, tm0, 1));
        tm0 = fmaxf(tm0, __shfl_xor_sync(0xffffffffu, tm0, 2));
        tm1 = fmaxf(tm1, __shfl_xor_sync(0xffffffffu, tm1, 1));
        tm1 = fmaxf(tm1, __shfl_xor_sync(0xffffffffu, tm1, 2));
        float mn0 = fmaxf(m0, tm0), mn1 = fmaxf(m1, tm1);
        float al0 = ex2(m0 - mn0), al1 = ex2(m1 - mn1);
        m0 = mn0; m1 = mn1;
        l0 *= al0; l1 *= al1;
#pragma unroll
        for (int dt = 0; dt < 8; dt++) {
            O[dt][0] *= al0; O[dt][1] *= al0;
            O[dt][2] *= al1; O[dt][3] *= al1;
        }

        // P split via pack-then-bit-unpack; l from unrounded p
        float rs0 = 0.0f, rs1 = 0.0f;
        uint32_t aPh[4][4], aPl[4][4];
#pragma unroll
        for (int nt = 0; nt < 8; nt++) {
            float p0 = ex2(S[nt][0] - m0);
            float p1 = ex2(S[nt][1] - m0);
            float p2 = ex2(S[nt][2] - m1);
            float p3 = ex2(S[nt][3] - m1);
            rs0 += p0 + p1; rs1 += p2 + p3;
            int kk = nt >> 1, hf = (nt & 1) * 2;
            uint32_t h01 = bf16x2_pack(p0, p1);
            uint32_t h23 = bf16x2_pack(p2, p3);
            aPh[kk][hf + 0] = h01;
            aPh[kk][hf + 1] = h23;
            float p0h = __uint_as_float(h01 << 16);
            float p1h = __uint_as_float(h01 & 0xFFFF0000u);
            float p2h = __uint_as_float(h23 << 16);
            float p3h = __uint_as_float(h23 & 0xFFFF0000u);
            aPl[kk][hf + 0] = bf16x2_pack(p0 - p0h, p1 - p1h);
            aPl[kk][hf + 1] = bf16x2_pack(p2 - p2h, p3 - p3h);
        }
        rs0 += __shfl_xor_sync(0xffffffffu, rs0, 1);
        rs0 += __shfl_xor_sync(0xffffffffu, rs0, 2);
        rs1 += __shfl_xor_sync(0xffffffffu, rs1, 1);
        rs1 += __shfl_xor_sync(0xffffffffu, rs1, 2);
        l0 += rs0; l1 += rs1;

        // O += Ph*Vh + Ph*Vl + Pl*Vh
#pragma unroll
        for (int kk = 0; kk < 4; kk++) {
            const int kb = kk * 16;
#pragma unroll
            for (int p = 0; p < 4; p++) {
                uint32_t vh[4], vl[4];
                int off = (kb + vt_ro) * APAD + p * 16 + vt_co;
                ldmatrix_x4_trans(vh, smem_u32(pVh + off));
                ldmatrix_x4_trans(vl, smem_u32(pVl + off));
                mma_bf16(O[2*p],   aPh[kk][0], aPh[kk][1], aPh[kk][2], aPh[kk][3], vh[0], vh[1]);
                mma_bf16(O[2*p+1], aPh[kk][0], aPh[kk][1], aPh[kk][2], aPh[kk][3], vh[2], vh[3]);
                mma_bf16(O[2*p],   aPh[kk][0], aPh[kk][1], aPh[kk][2], aPh[kk][3], vl[0], vl[1]);
                mma_bf16(O[2*p+1], aPh[kk][0], aPh[kk][1], aPh[kk][2], aPh[kk][3], vl[2], vl[3]);
                mma_bf16(O[2*p],   aPl[kk][0], aPl[kk][1], aPl[kk][2], aPl[kk][3], vh[0], vh[1]);
                mma_bf16(O[2*p+1], aPl[kk][0], aPl[kk][1], aPl[kk][2], aPl[kk][3], vh[2], vh[3]);
            }
        }
    }

    // Epilogue: bf16 hi/lo via pack-unpack
    float inv0 = 1.0f / l0, inv1 = 1.0f / l1;
    int r0 = q0 + w * 16 + g, r1 = r0 + 8;
    size_t o0 = ((size_t)(b * Tdim + r0)) * Cdim + h * Ddim;
    size_t o1 = ((size_t)(b * Tdim + r1)) * Cdim + h * Ddim;
#pragma unroll
    for (int dt = 0; dt < 8; dt++) {
        int d = dt * 8 + tig * 2;
        float v00 = O[dt][0] * inv0, v01 = O[dt][1] * inv0;
        float v10 = O[dt][2] * inv1, v11 = O[dt][3] * inv1;
        uint32_t h0 = bf16x2_pack(v00, v01);
        uint32_t h1 = bf16x2_pack(v10, v11);
        float h00 = __uint_as_float(h0 << 16);
        float h01 = __uint_as_float(h0 & 0xFFFF0000u);
        float h10 = __uint_as_float(h1 << 16);
        float h11 = __uint_as_float(h1 & 0xFFFF0000u);
        *reinterpret_cast<uint32_t*>(outHi + o0 + d) = h0;
        *reinterpret_cast<uint32_t*>(outHi + o1 + d) = h1;
        *reinterpret_cast<uint32_t*>(outLo + o0 + d) = bf16x2_pack(v00 - h00, v01 - h01);
        *reinterpret_cast<uint32_t*>(outLo + o1 + d) = bf16x2_pack(v10 - h10, v11 - h11);
    }
}

// ---------------------------------------------------------------------------
extern "C" void kernel_launch(void* const* d_in, const int* in_sizes, int n_in,
                              void* d_out, int out_size)
{
    (void)in_sizes; (void)n_in; (void)out_size;
    const float* x      = (const float*)d_in[0];
    const float* W_attn = (const float*)d_in[1];
    const float* b_attn = (const float*)d_in[2];
    const float* W_proj = (const float*)d_in[3];
    const float* b_proj = (const float*)d_in[4];
    float* out = (float*)d_out;

    unsigned short *x_hi, *x_lo, *Wa_hi, *Wa_lo, *Wp_hi, *Wp_lo, *ah_hi, *ah_lo, *qkv_hi, *qkv_lo;
    cudaGetSymbolAddress((void**)&x_hi, g_x_hi);
    cudaGetSymbolAddress((void**)&x_lo, g_x_lo);
    cudaGetSymbolAddress((void**)&Wa_hi, g_Wa_hi);
    cudaGetSymbolAddress((void**)&Wa_lo, g_Wa_lo);
    cudaGetSymbolAddress((void**)&Wp_hi, g_Wp_hi);
    cudaGetSymbolAddress((void**)&Wp_lo, g_Wp_lo);
    cudaGetSymbolAddress((void**)&ah_hi, g_ah_hi);
    cudaGetSymbolAddress((void**)&ah_lo, g_ah_lo);
    cudaGetSymbolAddress((void**)&qkv_hi, g_qkv_hi);
    cudaGetSymbolAddress((void**)&qkv_lo, g_qkv_lo);

    cudaFuncSetAttribute(gemm_mma_kernel,
                         cudaFuncAttributeMaxDynamicSharedMemorySize, GEMM_SMEM_BYTES);
    cudaFuncSetAttribute(attn_mma_kernel,
                         cudaFuncAttributeMaxDynamicSharedMemorySize, ATTN_SMEM_BYTES);

    // 0) Fused input splits
    fused_split_kernel<<<SPLIT_BLOCKS, 256>>>(
        x, x_hi, x_lo, W_attn, Wa_hi, Wa_lo, W_proj, Wp_hi, Wp_lo);
    // 1) QKV = x @ W_attn + b_attn -> bf16 hi/lo; Q columns pre-scaled
    gemm_mma_kernel<<<dim3(C3 / BN, Mrows / BM), 256, GEMM_SMEM_BYTES>>>(
        x_hi, x_lo, Wa_hi, Wa_lo, b_attn, nullptr, qkv_hi, qkv_lo,
        Mrows, C3, Cdim, Cdim, QSCALE);
    // 2) Tensor-core flash attention -> bf16 hi/lo
    attn_mma_kernel<<<dim3(Tdim / 64, Bdim * Hdim), 128, ATTN_SMEM_BYTES>>>(
        qkv_hi, qkv_lo, ah_hi, ah_lo);
    // 3) out = att @ W_proj + b_proj (fp32 epilogue)
    gemm_mma_kernel<<<dim3(Cdim / BN, Mrows / BM), 256, GEMM_SMEM_BYTES>>>(
        ah_hi, ah_lo, Wp_hi, Wp_lo, b_proj, out, nullptr, nullptr,
        Mrows, Cdim, Cdim, 0, 1.0f);
}

// round 16
// speedup vs baseline: 1.8950x; 1.0190x over previous
#include <cuda_runtime.h>
#include <cuda_bf16.h>
#include <cstdint>
#include <cstddef>

#define Bdim 4
#define Tdim 2048
#define Cdim 1024
#define Hdim 16
#define Ddim 64
#define C3   3072
#define Mrows 8192

// bf16 hi/lo scratch
__device__ unsigned short g_x_hi[(size_t)Mrows * Cdim];
__device__ unsigned short g_x_lo[(size_t)Mrows * Cdim];
__device__ unsigned short g_Wa_hi[(size_t)C3 * Cdim];   // transposed [N=3072][K=1024]
__device__ unsigned short g_Wa_lo[(size_t)C3 * Cdim];
__device__ unsigned short g_Wp_hi[(size_t)Cdim * Cdim]; // transposed [N=1024][K=1024]
__device__ unsigned short g_Wp_lo[(size_t)Cdim * Cdim];
__device__ unsigned short g_ah_hi[(size_t)Mrows * Cdim];
__device__ unsigned short g_ah_lo[(size_t)Mrows * Cdim];
__device__ unsigned short g_qkv_hi[(size_t)Mrows * C3];
__device__ unsigned short g_qkv_lo[(size_t)Mrows * C3];

// ---------------------------------------------------------------------------
// PTX helpers (compute_103-safe)
// ---------------------------------------------------------------------------
__device__ __forceinline__ void mma_bf16(float* d,
    uint32_t a0, uint32_t a1, uint32_t a2, uint32_t a3,
    uint32_t b0, uint32_t b1)
{
    asm volatile(
        "mma.sync.aligned.m16n8k16.row.col.f32.bf16.bf16.f32 "
        "{%0,%1,%2,%3}, {%4,%5,%6,%7}, {%8,%9}, {%0,%1,%2,%3};"
        : "+f"(d[0]), "+f"(d[1]), "+f"(d[2]), "+f"(d[3])
        : "r"(a0), "r"(a1), "r"(a2), "r"(a3), "r"(b0), "r"(b1));
}
__device__ __forceinline__ void ldmatrix_x4(uint32_t* r, uint32_t addr) {
    asm volatile("ldmatrix.sync.aligned.m8n8.x4.shared.b16 {%0,%1,%2,%3}, [%4];"
        : "=r"(r[0]), "=r"(r[1]), "=r"(r[2]), "=r"(r[3]) : "r"(addr));
}
__device__ __forceinline__ void ldmatrix_x4_trans(uint32_t* r, uint32_t addr) {
    asm volatile("ldmatrix.sync.aligned.m8n8.x4.trans.shared.b16 {%0,%1,%2,%3}, [%4];"
        : "=r"(r[0]), "=r"(r[1]), "=r"(r[2]), "=r"(r[3]) : "r"(addr));
}
__device__ __forceinline__ uint32_t smem_u32(const void* p) {
    return (uint32_t)__cvta_generic_to_shared(p);
}
__device__ __forceinline__ uint32_t bf16x2_pack(float lo, float hi) {
    uint32_t r;
    asm("cvt.rn.bf16x2.f32 %0, %1, %2;" : "=r"(r) : "f"(hi), "f"(lo));
    return r;
}
__device__ __forceinline__ float bf16_round(float x) {
    __nv_bfloat16 h = __float2bfloat16(x);
    return __bfloat162float(h);
}
__device__ __forceinline__ float ex2(float x) {
    float r;
    asm("ex2.approx.f32 %0, %1;" : "=f"(r) : "f"(x));
    return r;
}
__device__ __forceinline__ void cp_async16(void* smem_dst, const void* gsrc) {
    uint32_t sa = smem_u32(smem_dst);
    asm volatile("cp.async.cg.shared.global [%0], [%1], 16;" :: "r"(sa), "l"(gsrc) : "memory");
}
__device__ __forceinline__ void cp_async_commit() {
    asm volatile("cp.async.commit_group;" ::: "memory");
}
template<int N> __device__ __forceinline__ void cp_async_wait() {
    asm volatile("cp.async.wait_group %0;" :: "n"(N) : "memory");
}

// S pre-scaled by 0.125 * log2(e) via the QKV epilogue Q-column scale.
#define QSCALE 0.18033688011112042f

// ---------------------------------------------------------------------------
// Fused input split (one launch: x vectorized + Wa^T + Wp^T)
// ---------------------------------------------------------------------------
#define XBLK 8192
#define WABLK 3072
#define WPBLK 1024
#define SPLIT_BLOCKS (XBLK + WABLK + WPBLK)

__device__ __forceinline__ void splitT_tile(
    const float* __restrict__ W, unsigned short* __restrict__ hiT,
    unsigned short* __restrict__ loT, int K, int N, int bn, int bk)
{
    __shared__ float t[32][33];
    int tx = threadIdx.x & 31;
    int ty = threadIdx.x >> 5;
#pragma unroll
    for (int i = ty; i < 32; i += 8)
        t[i][tx] = W[(size_t)(bk + i) * N + bn + tx];
    __syncthreads();
#pragma unroll
    for (int i = ty; i < 32; i += 8) {
        float x = t[tx][i];
        float h = bf16_round(x);
        float l = x - h;
        size_t o = (size_t)(bn + i) * K + bk + tx;
        uint32_t hl = bf16x2_pack(h, l);
        hiT[o] = (unsigned short)(hl & 0xFFFF);
        loT[o] = (unsigned short)(hl >> 16);
    }
}

__global__ __launch_bounds__(256) void fused_split_kernel(
    const float* __restrict__ x, unsigned short* __restrict__ x_hi,
    unsigned short* __restrict__ x_lo,
    const float* __restrict__ Wa, unsigned short* __restrict__ Wa_hi,
    unsigned short* __restrict__ Wa_lo,
    const float* __restrict__ Wp, unsigned short* __restrict__ Wp_hi,
    unsigned short* __restrict__ Wp_lo)
{
    int bid = blockIdx.x;
    if (bid < XBLK) {
        int i4 = bid * 256 + threadIdx.x;
        float4 v = reinterpret_cast<const float4*>(x)[i4];
        float h0 = bf16_round(v.x), h1 = bf16_round(v.y);
        float h2 = bf16_round(v.z), h3 = bf16_round(v.w);
        uint2 hp, lp;
        hp.x = bf16x2_pack(h0, h1);
        hp.y = bf16x2_pack(h2, h3);
        lp.x = bf16x2_pack(v.x - h0, v.y - h1);
        lp.y = bf16x2_pack(v.z - h2, v.w - h3);
        reinterpret_cast<uint2*>(x_hi)[i4] = hp;
        reinterpret_cast<uint2*>(x_lo)[i4] = lp;
    } else if (bid < XBLK + WABLK) {
        int b2 = bid - XBLK;
        splitT_tile(Wa, Wa_hi, Wa_lo, Cdim, C3, (b2 % 96) * 32, (b2 / 96) * 32);
    } else {
        int b3 = bid - XBLK - WABLK;
        splitT_tile(Wp, Wp_hi, Wp_lo, Cdim, Cdim, (b3 & 31) * 32, (b3 >> 5) * 32);
    }
}

// ---------------------------------------------------------------------------
// GEMM: 2-stage cp.async pipeline, PAD=40 (16B-aligned rows), ldmatrix frags,
// accumulator-interleaved MMAs. (round-13/15 validated, frozen)
// ---------------------------------------------------------------------------
#define BM 128
#define BN 128
#define BK 32
#define PAD 40
#define GTILE (128 * PAD)
#define GBUF  (4 * GTILE)
#define GEMM_SMEM_BYTES (2 * GBUF * 2)

__global__ __launch_bounds__(256, 2) void gemm_mma_kernel(
    const unsigned short* __restrict__ Ah, const unsigned short* __restrict__ Al,
    const unsigned short* __restrict__ Bh, const unsigned short* __restrict__ Bl,
    const float* __restrict__ bias, float* __restrict__ C,
    unsigned short* __restrict__ OHi, unsigned short* __restrict__ OLo,
    int M, int N, int K, int qcols, float qscale)
{
    extern __shared__ unsigned short sm[];

    const int tid = threadIdx.x;
    const int wid = tid >> 5;
    const int lane = tid & 31;
    const int g   = lane >> 2;
    const int tig = lane & 3;
    const int lgrp = lane >> 3;
    const int lrow = lane & 7;
    const int wm  = wid & 3;
    const int wn  = wid >> 2;
    const int bm  = blockIdx.y * BM;
    const int bn  = blockIdx.x * BN;

    float acc[2][8][4];
#pragma unroll
    for (int i = 0; i < 2; i++)
#pragma unroll
        for (int j = 0; j < 8; j++)
#pragma unroll
            for (int v = 0; v < 4; v++) acc[i][j][v] = 0.0f;

    const int lr = tid >> 1;
    const int lh = tid & 1;
    const int nk = K / BK;

    auto load_tile = [&](int s, int buf) {
        const int k0 = s * BK;
        unsigned short* base = sm + buf * GBUF + lr * PAD + lh * 16;
        const size_t aoff = (size_t)(bm + lr) * K + k0 + lh * 16;
        const size_t boff = (size_t)(bn + lr) * K + k0 + lh * 16;
        cp_async16(base + 0 * GTILE,     Ah + aoff);
        cp_async16(base + 0 * GTILE + 8, Ah + aoff + 8);
        cp_async16(base + 1 * GTILE,     Al + aoff);
        cp_async16(base + 1 * GTILE + 8, Al + aoff + 8);
        cp_async16(base + 2 * GTILE,     Bh + boff);
        cp_async16(base + 2 * GTILE + 8, Bh + boff + 8);
        cp_async16(base + 3 * GTILE,     Bl + boff);
        cp_async16(base + 3 * GTILE + 8, Bl + boff + 8);
    };

    load_tile(0, 0);
    cp_async_commit();

    const int a_ro = (lgrp & 1) * 8 + lrow;
    const int a_co = (lgrp >> 1) * 8;
    const int b_ro = (lgrp >> 1) * 8 + lrow;
    const int b_co = (lgrp & 1) * 8;

    for (int s = 0; s < nk; s++) {
        cp_async_wait<0>();
        __syncthreads();
        if (s + 1 < nk) {
            load_tile(s + 1, (s + 1) & 1);
            cp_async_commit();
        }

        const unsigned short* pAh = sm + (s & 1) * GBUF;
        const unsigned short* pAl = pAh + GTILE;
        const unsigned short* pBh = pAl + GTILE;
        const unsigned short* pBl = pBh + GTILE;

#pragma unroll
        for (int ks = 0; ks < 2; ks++) {
            const int kb = ks * 16;
            uint32_t ah[2][4], al[2][4];
#pragma unroll
            for (int mt = 0; mt < 2; mt++) {
                int off = (wm * 32 + mt * 16 + a_ro) * PAD + kb + a_co;
                ldmatrix_x4(ah[mt], smem_u32(pAh + off));
                ldmatrix_x4(al[mt], smem_u32(pAl + off));
            }
#pragma unroll
            for (int p = 0; p < 4; p++) {
                int off = (wn * 64 + p * 16 + b_ro) * PAD + kb + b_co;
                uint32_t bh[4], bl[4];
                ldmatrix_x4(bh, smem_u32(pBh + off));
                ldmatrix_x4(bl, smem_u32(pBl + off));
                mma_bf16(acc[0][2*p],   ah[0][0], ah[0][1], ah[0][2], ah[0][3], bh[0], bh[1]);
                mma_bf16(acc[1][2*p],   ah[1][0], ah[1][1], ah[1][2], ah[1][3], bh[0], bh[1]);
                mma_bf16(acc[0][2*p+1], ah[0][0], ah[0][1], ah[0][2], ah[0][3], bh[2], bh[3]);
                mma_bf16(acc[1][2*p+1], ah[1][0], ah[1][1], ah[1][2], ah[1][3], bh[2], bh[3]);
                mma_bf16(acc[0][2*p],   ah[0][0], ah[0][1], ah[0][2], ah[0][3], bl[0], bl[1]);
                mma_bf16(acc[1][2*p],   ah[1][0], ah[1][1], ah[1][2], ah[1][3], bl[0], bl[1]);
                mma_bf16(acc[0][2*p+1], ah[0][0], ah[0][1], ah[0][2], ah[0][3], bl[2], bl[3]);
                mma_bf16(acc[1][2*p+1], ah[1][0], ah[1][1], ah[1][2], ah[1][3], bl[2], bl[3]);
                mma_bf16(acc[0][2*p],   al[0][0], al[0][1], al[0][2], al[0][3], bh[0], bh[1]);
                mma_bf16(acc[1][2*p],   al[1][0], al[1][1], al[1][2], al[1][3], bh[0], bh[1]);
                mma_bf16(acc[0][2*p+1], al[0][0], al[0][1], al[0][2], al[0][3], bh[2], bh[3]);
                mma_bf16(acc[1][2*p+1], al[1][0], al[1][1], al[1][2], al[1][3], bh[2], bh[3]);
            }
        }
    }

    // Epilogue
#pragma unroll
    for (int mt = 0; mt < 2; mt++) {
        int r0 = bm + wm * 32 + mt * 16 + g;
        int r1 = r0 + 8;
#pragma unroll
        for (int nt = 0; nt < 8; nt++) {
            int col = bn + wn * 64 + nt * 8 + tig * 2;
            float b0 = bias[col], b1 = bias[col + 1];
            float v00 = acc[mt][nt][0] + b0, v01 = acc[mt][nt][1] + b1;
            float v10 = acc[mt][nt][2] + b0, v11 = acc[mt][nt][3] + b1;
            if (C) {
                *reinterpret_cast<float2*>(C + (size_t)r0 * N + col) = make_float2(v00, v01);
                *reinterpret_cast<float2*>(C + (size_t)r1 * N + col) = make_float2(v10, v11);
            } else {
                float sc = (col < qcols) ? qscale : 1.0f;
                v00 *= sc; v01 *= sc; v10 *= sc; v11 *= sc;
                uint32_t h0 = bf16x2_pack(v00, v01);
                uint32_t h1 = bf16x2_pack(v10, v11);
                float h00 = __uint_as_float(h0 << 16);
                float h01 = __uint_as_float(h0 & 0xFFFF0000u);
                float h10 = __uint_as_float(h1 << 16);
                float h11 = __uint_as_float(h1 & 0xFFFF0000u);
                *reinterpret_cast<uint32_t*>(OHi + (size_t)r0 * N + col) = h0;
                *reinterpret_cast<uint32_t*>(OHi + (size_t)r1 * N + col) = h1;
                *reinterpret_cast<uint32_t*>(OLo + (size_t)r0 * N + col) = bf16x2_pack(v00 - h00, v01 - h01);
                *reinterpret_cast<uint32_t*>(OLo + (size_t)r1 * N + col) = bf16x2_pack(v10 - h10, v11 - h11);
            }
        }
    }
}

// ---------------------------------------------------------------------------
// Tensor-core causal flash attention (64 q-rows, 128 thr, cp.async 2-stage).
// __launch_bounds__(128, 3): cap regs at 170 so 3 CTAs/SM fit (smem allows 3).
// ---------------------------------------------------------------------------
#define APAD 72
#define ATILE (64 * APAD)
#define ABUF  (4 * ATILE)
#define ATTN_SMEM_BYTES (2 * ABUF * 2)

__global__ __launch_bounds__(128, 3) void attn_mma_kernel(
    const unsigned short* __restrict__ qvh, const unsigned short* __restrict__ qvl,
    unsigned short* __restrict__ outHi, unsigned short* __restrict__ outLo)
{
    extern __shared__ unsigned short smem[];

    const int tid = threadIdx.x;
    const int w = tid >> 5, lane = tid & 31;
    const int g = lane >> 2, tig = lane & 3;
    const int lgrp = lane >> 3, lrow = lane & 7;
    const int bh = blockIdx.y, b = bh >> 4, h = bh & 15;
    const int qt = (gridDim.x - 1) - blockIdx.x;   // heavy-first
    const int q0 = qt * 64;

    auto load_kv = [&](int jb, int st) {
        int row = tid >> 1, half = tid & 1;
        size_t gk = ((size_t)(b * Tdim + jb * 64 + row)) * C3 + Cdim + h * Ddim + half * 32;
        size_t gv = gk + Cdim;
        unsigned short* base = smem + st * ABUF + row * APAD + half * 32;
#pragma unroll
        for (int i = 0; i < 4; i++) {
            cp_async16(base + 0 * ATILE + i * 8, qvh + gk + i * 8);
            cp_async16(base + 1 * ATILE + i * 8, qvl + gk + i * 8);
            cp_async16(base + 2 * ATILE + i * 8, qvh + gv + i * 8);
            cp_async16(base + 3 * ATILE + i * 8, qvl + gv + i * 8);
        }
    };

    // Stage Q through stage-1 K buffers
    {
        int row = tid >> 1, half = tid & 1;
        size_t go = ((size_t)(b * Tdim + q0 + row)) * C3 + h * Ddim + half * 32;
        const uint4* gh = reinterpret_cast<const uint4*>(qvh + go);
        const uint4* gl = reinterpret_cast<const uint4*>(qvl + go);
        uint4* dh = reinterpret_cast<uint4*>(smem + ABUF + 0 * ATILE + row * APAD + half * 32);
        uint4* dl = reinterpret_cast<uint4*>(smem + ABUF + 1 * ATILE + row * APAD + half * 32);
#pragma unroll
        for (int i = 0; i < 4; i++) { dh[i] = gh[i]; dl[i] = gl[i]; }
    }
    __syncthreads();

    // Hoist Q fragments
    uint32_t aqh[4][4], aql[4][4];
    {
        const unsigned short* pQh = smem + ABUF;
        const unsigned short* pQl = pQh + ATILE;
        const int ro = w * 16 + (lgrp & 1) * 8 + lrow;
#pragma unroll
        for (int kk = 0; kk < 4; kk++) {
            int co = kk * 16 + (lgrp >> 1) * 8;
            ldmatrix_x4(aqh[kk], smem_u32(pQh + ro * APAD + co));
            ldmatrix_x4(aql[kk], smem_u32(pQl + ro * APAD + co));
        }
    }

    load_kv(0, 0);
    cp_async_commit();

    float m0 = -1e30f, m1 = -1e30f, l0 = 0.0f, l1 = 0.0f;
    float O[8][4];
#pragma unroll
    for (int dt = 0; dt < 8; dt++)
#pragma unroll
        for (int v = 0; v < 4; v++) O[dt][v] = 0.0f;

    const int kb_ro = (lgrp >> 1) * 8 + lrow;
    const int kb_co = (lgrp & 1) * 8;
    const int vt_ro = (lgrp & 1) * 8 + lrow;
    const int vt_co = (lgrp >> 1) * 8;

    for (int jb = 0; jb <= qt; jb++) {
        cp_async_wait<0>();
        __syncthreads();
        if (jb + 1 <= qt) {
            load_kv(jb + 1, (jb + 1) & 1);
            cp_async_commit();
        }

        const unsigned short* pKh = smem + (jb & 1) * ABUF;
        const unsigned short* pKl = pKh + ATILE;
        const unsigned short* pVh = pKl + ATILE;
        const unsigned short* pVl = pVh + ATILE;

        // S = Q K^T (pre-scaled to exp2 domain)
        float S[8][4];
#pragma unroll
        for (int nt = 0; nt < 8; nt++)
#pragma unroll
            for (int v = 0; v < 4; v++) S[nt][v] = 0.0f;
#pragma unroll
        for (int kk = 0; kk < 4; kk++) {
            const int kb = kk * 16;
#pragma unroll
            for (int p = 0; p < 4; p++) {
                uint32_t kh[4], kl[4];
                int off = (p * 16 + kb_ro) * APAD + kb + kb_co;
                ldmatrix_x4(kh, smem_u32(pKh + off));
                ldmatrix_x4(kl, smem_u32(pKl + off));
                mma_bf16(S[2*p],   aqh[kk][0], aqh[kk][1], aqh[kk][2], aqh[kk][3], kh[0], kh[1]);
                mma_bf16(S[2*p+1], aqh[kk][0], aqh[kk][1], aqh[kk][2], aqh[kk][3], kh[2], kh[3]);
                mma_bf16(S[2*p],   aqh[kk][0], aqh[kk][1], aqh[kk][2], aqh[kk][3], kl[0], kl[1]);
                mma_bf16(S[2*p+1], aqh[kk][0], aqh[kk][1], aqh[kk][2], aqh[kk][3], kl[2], kl[3]);
                mma_bf16(S[2*p],   aql[kk][0], aql[kk][1], aql[kk][2], aql[kk][3], kh[0], kh[1]);
                mma_bf16(S[2*p+1], aql[kk][0], aql[kk][1], aql[kk][2], aql[kk][3], kh[2], kh[3]);
            }
        }

        // Causal mask (diagonal tile only)
        if (jb == qt) {
            const int lq0 = w * 16 + g, lq1 = lq0 + 8;
#pragma unroll
            for (int nt = 0; nt < 8; nt++) {
                int lj = nt * 8 + tig * 2;
                if (lj     > lq0) S[nt][0] = -1e30f;
                if (lj + 1 > lq0) S[nt][1] = -1e30f;
                if (lj     > lq1) S[nt][2] = -1e30f;
                if (lj + 1 > lq1) S[nt][3] = -1e30f;
            }
        }

        // Online softmax (exp2 domain)
        float tm0 = -1e30f, tm1 = -1e30f;
#pragma unroll
        for (int nt = 0; nt < 8; nt++) {
            tm0 = fmaxf(tm0, fmaxf(S[nt][0], S[nt][1]));
            tm1 = fmaxf(tm1, fmaxf(S[nt][2], S[nt][3]));
        }
        tm0 = fmaxf(tm0, __shfl_xor_sync(0xffffffffu, tm0, 1));
        tm0 = fmaxf(tm0, __shfl_xor_sync(0xffffffffu, tm0, 2));
        tm1 = fmaxf(tm1, __shfl_xor_sync(0xffffffffu, tm1, 1));
        tm1 = fmaxf(tm1, __shfl_xor_sync(0xffffffffu, tm1, 2));
        float mn0 = fmaxf(m0, tm0), mn1 = fmaxf(m1, tm1);
        float al0 = ex2(m0 - mn0), al1 = ex2(m1 - mn1);
        m0 = mn0; m1 = mn1;
        l0 *= al0; l1 *= al1;
#pragma unroll
        for (int dt = 0; dt < 8; dt++) {
            O[dt][0] *= al0; O[dt][1] *= al0;
            O[dt][2] *= al1; O[dt][3] *= al1;
        }

        // P split via pack-then-bit-unpack; l from unrounded p
        float rs0 = 0.0f, rs1 = 0.0f;
        uint32_t aPh[4][4], aPl[4][4];
#pragma unroll
        for (int nt = 0; nt < 8; nt++) {
            float p0 = ex2(S[nt][0] - m0);
            float p1 = ex2(S[nt][1] - m0);
            float p2 = ex2(S[nt][2] - m1);
            float p3 = ex2(S[nt][3] - m1);
            rs0 += p0 + p1; rs1 += p2 + p3;
            int kk = nt >> 1, hf = (nt & 1) * 2;
            uint32_t h01 = bf16x2_pack(p0, p1);
            uint32_t h23 = bf16x2_pack(p2, p3);
            aPh[kk][hf + 0] = h01;
            aPh[kk][hf + 1] = h23;
            float p0h = __uint_as_float(h01 << 16);
            float p1h = __uint_as_float(h01 & 0xFFFF0000u);
            float p2h = __uint_as_float(h23 << 16);
            float p3h = __uint_as_float(h23 & 0xFFFF0000u);
            aPl[kk][hf + 0] = bf16x2_pack(p0 - p0h, p1 - p1h);
            aPl[kk][hf + 1] = bf16x2_pack(p2 - p2h, p3 - p3h);
        }
        rs0 += __shfl_xor_sync(0xffffffffu, rs0, 1);
        rs0 += __shfl_xor_sync(0xffffffffu, rs0, 2);
        rs1 += __shfl_xor_sync(0xffffffffu, rs1, 1);
        rs1 += __shfl_xor_sync(0xffffffffu, rs1, 2);
        l0 += rs0; l1 += rs1;

        // O += Ph*Vh + Ph*Vl + Pl*Vh
#pragma unroll
        for (int kk = 0; kk < 4; kk++) {
            const int kb = kk * 16;
#pragma unroll
            for (int p = 0; p < 4; p++) {
                uint32_t vh[4], vl[4];
                int off = (kb + vt_ro) * APAD + p * 16 + vt_co;
                ldmatrix_x4_trans(vh, smem_u32(pVh + off));
                ldmatrix_x4_trans(vl, smem_u32(pVl + off));
                mma_bf16(O[2*p],   aPh[kk][0], aPh[kk][1], aPh[kk][2], aPh[kk][3], vh[0], vh[1]);
                mma_bf16(O[2*p+1], aPh[kk][0], aPh[kk][1], aPh[kk][2], aPh[kk][3], vh[2], vh[3]);
                mma_bf16(O[2*p],   aPh[kk][0], aPh[kk][1], aPh[kk][2], aPh[kk][3], vl[0], vl[1]);
                mma_bf16(O[2*p+1], aPh[kk][0], aPh[kk][1], aPh[kk][2], aPh[kk][3], vl[2], vl[3]);
                mma_bf16(O[2*p],   aPl[kk][0], aPl[kk][1], aPl[kk][2], aPl[kk][3], vh[0], vh[1]);
                mma_bf16(O[2*p+1], aPl[kk][0], aPl[kk][1], aPl[kk][2], aPl[kk][3], vh[2], vh[3]);
            }
        }
    }

    // Epilogue: bf16 hi/lo via pack-unpack
    float inv0 = 1.0f / l0, inv1 = 1.0f / l1;
    int r0 = q0 + w * 16 + g, r1 = r0 + 8;
    size_t o0 = ((size_t)(b * Tdim + r0)) * Cdim + h * Ddim;
    size_t o1 = ((size_t)(b * Tdim + r1)) * Cdim + h * Ddim;
#pragma unroll
    for (int dt = 0; dt < 8; dt++) {
        int d = dt * 8 + tig * 2;
        float v00 = O[dt][0] * inv0, v01 = O[dt][1] * inv0;
        float v10 = O[dt][2] * inv1, v11 = O[dt][3] * inv1;
        uint32_t h0 = bf16x2_pack(v00, v01);
        uint32_t h1 = bf16x2_pack(v10, v11);
        float h00 = __uint_as_float(h0 << 16);
        float h01 = __uint_as_float(h0 & 0xFFFF0000u);
        float h10 = __uint_as_float(h1 << 16);
        float h11 = __uint_as_float(h1 & 0xFFFF0000u);
        *reinterpret_cast<uint32_t*>(outHi + o0 + d) = h0;
        *reinterpret_cast<uint32_t*>(outHi + o1 + d) = h1;
        *reinterpret_cast<uint32_t*>(outLo + o0 + d) = bf16x2_pack(v00 - h00, v01 - h01);
        *reinterpret_cast<uint32_t*>(outLo + o1 + d) = bf16x2_pack(v10 - h10, v11 - h11);
    }
}

// ---------------------------------------------------------------------------
extern "C" void kernel_launch(void* const* d_in, const int* in_sizes, int n_in,
                              void* d_out, int out_size)
{
    (void)in_sizes; (void)n_in; (void)out_size;
    const float* x      = (const float*)d_in[0];
    const float* W_attn = (const float*)d_in[1];
    const float* b_attn = (const float*)d_in[2];
    const float* W_proj = (const float*)d_in[3];
    const float* b_proj = (const float*)d_in[4];
    float* out = (float*)d_out;

    unsigned short *x_hi, *x_lo, *Wa_hi, *Wa_lo, *Wp_hi, *Wp_lo, *ah_hi, *ah_lo, *qkv_hi, *qkv_lo;
    cudaGetSymbolAddress((void**)&x_hi, g_x_hi);
    cudaGetSymbolAddress((void**)&x_lo, g_x_lo);
    cudaGetSymbolAddress((void**)&Wa_hi, g_Wa_hi);
    cudaGetSymbolAddress((void**)&Wa_lo, g_Wa_lo);
    cudaGetSymbolAddress((void**)&Wp_hi, g_Wp_hi);
    cudaGetSymbolAddress((void**)&Wp_lo, g_Wp_lo);
    cudaGetSymbolAddress((void**)&ah_hi, g_ah_hi);
    cudaGetSymbolAddress((void**)&ah_lo, g_ah_lo);
    cudaGetSymbolAddress((void**)&qkv_hi, g_qkv_hi);
    cudaGetSymbolAddress((void**)&qkv_lo, g_qkv_lo);

    cudaFuncSetAttribute(gemm_mma_kernel,
                         cudaFuncAttributeMaxDynamicSharedMemorySize, GEMM_SMEM_BYTES);
    cudaFuncSetAttribute(attn_mma_kernel,
                         cudaFuncAttributeMaxDynamicSharedMemorySize, ATTN_SMEM_BYTES);

    // 0) Fused input splits
    fused_split_kernel<<<SPLIT_BLOCKS, 256>>>(
        x, x_hi, x_lo, W_attn, Wa_hi, Wa_lo, W_proj, Wp_hi, Wp_lo);
    // 1) QKV = x @ W_attn + b_attn -> bf16 hi/lo; Q columns pre-scaled
    gemm_mma_kernel<<<dim3(C3 / BN, Mrows / BM), 256, GEMM_SMEM_BYTES>>>(
        x_hi, x_lo, Wa_hi, Wa_lo, b_attn, nullptr, qkv_hi, qkv_lo,
        Mrows, C3, Cdim, Cdim, QSCALE);
    // 2) Tensor-core flash attention -> bf16 hi/lo
    attn_mma_kernel<<<dim3(Tdim / 64, Bdim * Hdim), 128, ATTN_SMEM_BYTES>>>(
        qkv_hi, qkv_lo, ah_hi, ah_lo);
    // 3) out = att @ W_proj + b_proj (fp32 epilogue)
    gemm_mma_kernel<<<dim3(Cdim / BN, Mrows / BM), 256, GEMM_SMEM_BYTES>>>(
        ah_hi, ah_lo, Wp_hi, Wp_lo, b_proj, out, nullptr, nullptr,
        Mrows, Cdim, Cdim, 0, 1.0f);
}

// round 17
// speedup vs baseline: 1.9484x; 1.0282x over previous
#include <cuda_runtime.h>
#include <cuda_bf16.h>
#include <cstdint>
#include <cstddef>

#define Bdim 4
#define Tdim 2048
#define Cdim 1024
#define Hdim 16
#define Ddim 64
#define C3   3072
#define Mrows 8192

// bf16 hi/lo scratch
__device__ unsigned short g_x_hi[(size_t)Mrows * Cdim];
__device__ unsigned short g_x_lo[(size_t)Mrows * Cdim];
__device__ unsigned short g_Wa_hi[(size_t)C3 * Cdim];   // transposed [N=3072][K=1024]
__device__ unsigned short g_Wa_lo[(size_t)C3 * Cdim];
__device__ unsigned short g_Wp_hi[(size_t)Cdim * Cdim]; // transposed [N=1024][K=1024]
__device__ unsigned short g_Wp_lo[(size_t)Cdim * Cdim];
__device__ unsigned short g_ah_hi[(size_t)Mrows * Cdim];
__device__ unsigned short g_ah_lo[(size_t)Mrows * Cdim];
__device__ unsigned short g_qkv_hi[(size_t)Mrows * C3];
__device__ unsigned short g_qkv_lo[(size_t)Mrows * C3];

// ---------------------------------------------------------------------------
// PTX helpers (compute_103-safe)
// ---------------------------------------------------------------------------
__device__ __forceinline__ void mma_bf16(float* d,
    uint32_t a0, uint32_t a1, uint32_t a2, uint32_t a3,
    uint32_t b0, uint32_t b1)
{
    asm volatile(
        "mma.sync.aligned.m16n8k16.row.col.f32.bf16.bf16.f32 "
        "{%0,%1,%2,%3}, {%4,%5,%6,%7}, {%8,%9}, {%0,%1,%2,%3};"
        : "+f"(d[0]), "+f"(d[1]), "+f"(d[2]), "+f"(d[3])
        : "r"(a0), "r"(a1), "r"(a2), "r"(a3), "r"(b0), "r"(b1));
}
__device__ __forceinline__ void ldmatrix_x4(uint32_t* r, uint32_t addr) {
    asm volatile("ldmatrix.sync.aligned.m8n8.x4.shared.b16 {%0,%1,%2,%3}, [%4];"
        : "=r"(r[0]), "=r"(r[1]), "=r"(r[2]), "=r"(r[3]) : "r"(addr));
}
__device__ __forceinline__ void ldmatrix_x4_trans(uint32_t* r, uint32_t addr) {
    asm volatile("ldmatrix.sync.aligned.m8n8.x4.trans.shared.b16 {%0,%1,%2,%3}, [%4];"
        : "=r"(r[0]), "=r"(r[1]), "=r"(r[2]), "=r"(r[3]) : "r"(addr));
}
__device__ __forceinline__ uint32_t smem_u32(const void* p) {
    return (uint32_t)__cvta_generic_to_shared(p);
}
__device__ __forceinline__ uint32_t bf16x2_pack(float lo, float hi) {
    uint32_t r;
    asm("cvt.rn.bf16x2.f32 %0, %1, %2;" : "=r"(r) : "f"(hi), "f"(lo));
    return r;
}
__device__ __forceinline__ float bf16_round(float x) {
    __nv_bfloat16 h = __float2bfloat16(x);
    return __bfloat162float(h);
}
__device__ __forceinline__ float ex2(float x) {
    float r;
    asm("ex2.approx.f32 %0, %1;" : "=f"(r) : "f"(x));
    return r;
}
__device__ __forceinline__ void cp_async16(void* smem_dst, const void* gsrc) {
    uint32_t sa = smem_u32(smem_dst);
    asm volatile("cp.async.cg.shared.global [%0], [%1], 16;" :: "r"(sa), "l"(gsrc) : "memory");
}
__device__ __forceinline__ void cp_async_commit() {
    asm volatile("cp.async.commit_group;" ::: "memory");
}
template<int N> __device__ __forceinline__ void cp_async_wait() {
    asm volatile("cp.async.wait_group %0;" :: "n"(N) : "memory");
}

// S pre-scaled by 0.125 * log2(e) via the QKV epilogue Q-column scale.
#define QSCALE 0.18033688011112042f

// ---------------------------------------------------------------------------
// Fused input split, vectorized:
//   x part: 4 float4 per thread, 2048 blocks
//   W part: 32(k) x 128(n) tiles, float4 row loads (512B/warp), smem transpose
// Block ranges: [0,2048) x | [2048,2816) Wa (24x32 tiles) | [2816,3072) Wp (8x32)
// ---------------------------------------------------------------------------
#define XBLK 2048
#define WABLK 768     // (C3/128=24) x (Cdim/32=32)
#define WPBLK 256     // (Cdim/128=8) x 32
#define SPLIT_BLOCKS (XBLK + WABLK + WPBLK)

__device__ __forceinline__ void splitT_tile_wide(
    const float* __restrict__ W, unsigned short* __restrict__ hiT,
    unsigned short* __restrict__ loT, int K, int N, int bn, int bk)
{
    // Load 32 rows x 128 cols with float4 (each row = 32 float4 = 1 warp-op)
    __shared__ float t[32][132];
    const int tid = threadIdx.x;
    {
        int r = tid >> 5;          // 0..7
        int c4 = tid & 31;         // 0..31 float4 slots
#pragma unroll
        for (int i = 0; i < 4; i++) {
            int row = r + i * 8;
            float4 v = *reinterpret_cast<const float4*>(
                W + (size_t)(bk + row) * N + bn + c4 * 4);
            t[row][c4 * 4 + 0] = v.x;
            t[row][c4 * 4 + 1] = v.y;
            t[row][c4 * 4 + 2] = v.z;
            t[row][c4 * 4 + 3] = v.w;
        }
    }
    __syncthreads();
    // Write transposed: thread handles (n = tid>>5*?); warp writes 32 consecutive k
    {
        int n = tid >> 5;          // 0..7 local n base (x16 below)
        int k = tid & 31;          // 0..31
#pragma unroll
        for (int i = 0; i < 16; i++) {
            int nl = n * 16 + i;   // 0..127
            float x = t[k][nl];
            float h = bf16_round(x);
            float l = x - h;
            size_t o = (size_t)(bn + nl) * K + bk + k;
            uint32_t hl = bf16x2_pack(h, l);
            hiT[o] = (unsigned short)(hl & 0xFFFF);
            loT[o] = (unsigned short)(hl >> 16);
        }
    }
}

__global__ __launch_bounds__(256) void fused_split_kernel(
    const float* __restrict__ x, unsigned short* __restrict__ x_hi,
    unsigned short* __restrict__ x_lo,
    const float* __restrict__ Wa, unsigned short* __restrict__ Wa_hi,
    unsigned short* __restrict__ Wa_lo,
    const float* __restrict__ Wp, unsigned short* __restrict__ Wp_hi,
    unsigned short* __restrict__ Wp_lo)
{
    int bid = blockIdx.x;
    if (bid < XBLK) {
        // x split: 4 float4 per thread, strided by blockDim for coalescing
#pragma unroll
        for (int i = 0; i < 4; i++) {
            int i4 = (bid * 4 + i) * 256 + threadIdx.x;
            float4 v = reinterpret_cast<const float4*>(x)[i4];
            float h0 = bf16_round(v.x), h1 = bf16_round(v.y);
            float h2 = bf16_round(v.z), h3 = bf16_round(v.w);
            uint2 hp, lp;
            hp.x = bf16x2_pack(h0, h1);
            hp.y = bf16x2_pack(h2, h3);
            lp.x = bf16x2_pack(v.x - h0, v.y - h1);
            lp.y = bf16x2_pack(v.z - h2, v.w - h3);
            reinterpret_cast<uint2*>(x_hi)[i4] = hp;
            reinterpret_cast<uint2*>(x_lo)[i4] = lp;
        }
    } else if (bid < XBLK + WABLK) {
        int b2 = bid - XBLK;
        splitT_tile_wide(Wa, Wa_hi, Wa_lo, Cdim, C3, (b2 % 24) * 128, (b2 / 24) * 32);
    } else {
        int b3 = bid - XBLK - WABLK;
        splitT_tile_wide(Wp, Wp_hi, Wp_lo, Cdim, Cdim, (b3 & 7) * 128, (b3 >> 3) * 32);
    }
}

// ---------------------------------------------------------------------------
// GEMM: 2-stage cp.async pipeline, PAD=40, ldmatrix frags, interleaved MMAs.
// ldmatrix base addresses hoisted (per-stage bases precomputed).
// ---------------------------------------------------------------------------
#define BM 128
#define BN 128
#define BK 32
#define PAD 40
#define GTILE (128 * PAD)
#define GBUF  (4 * GTILE)
#define GEMM_SMEM_BYTES (2 * GBUF * 2)

__global__ __launch_bounds__(256, 2) void gemm_mma_kernel(
    const unsigned short* __restrict__ Ah, const unsigned short* __restrict__ Al,
    const unsigned short* __restrict__ Bh, const unsigned short* __restrict__ Bl,
    const float* __restrict__ bias, float* __restrict__ C,
    unsigned short* __restrict__ OHi, unsigned short* __restrict__ OLo,
    int M, int N, int K, int qcols, float qscale)
{
    extern __shared__ unsigned short sm[];

    const int tid = threadIdx.x;
    const int wid = tid >> 5;
    const int lane = tid & 31;
    const int g   = lane >> 2;
    const int tig = lane & 3;
    const int lgrp = lane >> 3;
    const int lrow = lane & 7;
    const int wm  = wid & 3;
    const int wn  = wid >> 2;
    const int bm  = blockIdx.y * BM;
    const int bn  = blockIdx.x * BN;

    float acc[2][8][4];
#pragma unroll
    for (int i = 0; i < 2; i++)
#pragma unroll
        for (int j = 0; j < 8; j++)
#pragma unroll
            for (int v = 0; v < 4; v++) acc[i][j][v] = 0.0f;

    const int lr = tid >> 1;
    const int lh = tid & 1;
    const int nk = K / BK;

    auto load_tile = [&](int s, int buf) {
        const int k0 = s * BK;
        unsigned short* base = sm + buf * GBUF + lr * PAD + lh * 16;
        const size_t aoff = (size_t)(bm + lr) * K + k0 + lh * 16;
        const size_t boff = (size_t)(bn + lr) * K + k0 + lh * 16;
        cp_async16(base + 0 * GTILE,     Ah + aoff);
        cp_async16(base + 0 * GTILE + 8, Ah + aoff + 8);
        cp_async16(base + 1 * GTILE,     Al + aoff);
        cp_async16(base + 1 * GTILE + 8, Al + aoff + 8);
        cp_async16(base + 2 * GTILE,     Bh + boff);
        cp_async16(base + 2 * GTILE + 8, Bh + boff + 8);
        cp_async16(base + 3 * GTILE,     Bl + boff);
        cp_async16(base + 3 * GTILE + 8, Bl + boff + 8);
    };

    load_tile(0, 0);
    cp_async_commit();

    // Hoisted ldmatrix byte offsets (within a buffer) for both stages
    const uint32_t a_base = (uint32_t)((wm * 32 + (lgrp & 1) * 8 + lrow) * PAD + (lgrp >> 1) * 8) * 2;
    const uint32_t b_base = (uint32_t)((wn * 64 + (lgrp >> 1) * 8 + lrow) * PAD + (lgrp & 1) * 8) * 2;
    const uint32_t sm0 = smem_u32(sm);
    const uint32_t sm1 = sm0 + GBUF * 2;
    const uint32_t TB = GTILE * 2;   // tile stride in bytes

    for (int s = 0; s < nk; s++) {
        cp_async_wait<0>();
        __syncthreads();
        if (s + 1 < nk) {
            load_tile(s + 1, (s + 1) & 1);
            cp_async_commit();
        }

        const uint32_t stage = (s & 1) ? sm1 : sm0;
        const uint32_t aAh = stage + a_base;
        const uint32_t aAl = aAh + TB;
        const uint32_t aBh = stage + 2 * TB + b_base;
        const uint32_t aBl = aBh + TB;

#pragma unroll
        for (int ks = 0; ks < 2; ks++) {
            const uint32_t kb = ks * 32;   // 16 shorts = 32 bytes
            uint32_t ah[2][4], al[2][4];
#pragma unroll
            for (int mt = 0; mt < 2; mt++) {
                uint32_t off = mt * (16 * PAD * 2) + kb;
                ldmatrix_x4(ah[mt], aAh + off);
                ldmatrix_x4(al[mt], aAl + off);
            }
#pragma unroll
            for (int p = 0; p < 4; p++) {
                uint32_t off = p * (16 * PAD * 2) + kb;
                uint32_t bh[4], bl[4];
                ldmatrix_x4(bh, aBh + off);
                ldmatrix_x4(bl, aBl + off);
                mma_bf16(acc[0][2*p],   ah[0][0], ah[0][1], ah[0][2], ah[0][3], bh[0], bh[1]);
                mma_bf16(acc[1][2*p],   ah[1][0], ah[1][1], ah[1][2], ah[1][3], bh[0], bh[1]);
                mma_bf16(acc[0][2*p+1], ah[0][0], ah[0][1], ah[0][2], ah[0][3], bh[2], bh[3]);
                mma_bf16(acc[1][2*p+1], ah[1][0], ah[1][1], ah[1][2], ah[1][3], bh[2], bh[3]);
                mma_bf16(acc[0][2*p],   ah[0][0], ah[0][1], ah[0][2], ah[0][3], bl[0], bl[1]);
                mma_bf16(acc[1][2*p],   ah[1][0], ah[1][1], ah[1][2], ah[1][3], bl[0], bl[1]);
                mma_bf16(acc[0][2*p+1], ah[0][0], ah[0][1], ah[0][2], ah[0][3], bl[2], bl[3]);
                mma_bf16(acc[1][2*p+1], ah[1][0], ah[1][1], ah[1][2], ah[1][3], bl[2], bl[3]);
                mma_bf16(acc[0][2*p],   al[0][0], al[0][1], al[0][2], al[0][3], bh[0], bh[1]);
                mma_bf16(acc[1][2*p],   al[1][0], al[1][1], al[1][2], al[1][3], bh[0], bh[1]);
                mma_bf16(acc[0][2*p+1], al[0][0], al[0][1], al[0][2], al[0][3], bh[2], bh[3]);
                mma_bf16(acc[1][2*p+1], al[1][0], al[1][1], al[1][2], al[1][3], bh[2], bh[3]);
            }
        }
    }

    // Epilogue
#pragma unroll
    for (int mt = 0; mt < 2; mt++) {
        int r0 = bm + wm * 32 + mt * 16 + g;
        int r1 = r0 + 8;
#pragma unroll
        for (int nt = 0; nt < 8; nt++) {
            int col = bn + wn * 64 + nt * 8 + tig * 2;
            float b0 = bias[col], b1 = bias[col + 1];
            float v00 = acc[mt][nt][0] + b0, v01 = acc[mt][nt][1] + b1;
            float v10 = acc[mt][nt][2] + b0, v11 = acc[mt][nt][3] + b1;
            if (C) {
                *reinterpret_cast<float2*>(C + (size_t)r0 * N + col) = make_float2(v00, v01);
                *reinterpret_cast<float2*>(C + (size_t)r1 * N + col) = make_float2(v10, v11);
            } else {
                float sc = (col < qcols) ? qscale : 1.0f;
                v00 *= sc; v01 *= sc; v10 *= sc; v11 *= sc;
                uint32_t h0 = bf16x2_pack(v00, v01);
                uint32_t h1 = bf16x2_pack(v10, v11);
                float h00 = __uint_as_float(h0 << 16);
                float h01 = __uint_as_float(h0 & 0xFFFF0000u);
                float h10 = __uint_as_float(h1 << 16);
                float h11 = __uint_as_float(h1 & 0xFFFF0000u);
                *reinterpret_cast<uint32_t*>(OHi + (size_t)r0 * N + col) = h0;
                *reinterpret_cast<uint32_t*>(OHi + (size_t)r1 * N + col) = h1;
                *reinterpret_cast<uint32_t*>(OLo + (size_t)r0 * N + col) = bf16x2_pack(v00 - h00, v01 - h01);
                *reinterpret_cast<uint32_t*>(OLo + (size_t)r1 * N + col) = bf16x2_pack(v10 - h10, v11 - h11);
            }
        }
    }
}

// ---------------------------------------------------------------------------
// Tensor-core causal flash attention (64 q-rows, 128 thr, cp.async 2-stage,
// 3 CTAs/SM). exp2-domain softmax; pack-unpack splits. (round-16 validated)
// ---------------------------------------------------------------------------
#define APAD 72
#define ATILE (64 * APAD)
#define ABUF  (4 * ATILE)
#define ATTN_SMEM_BYTES (2 * ABUF * 2)

__global__ __launch_bounds__(128, 3) void attn_mma_kernel(
    const unsigned short* __restrict__ qvh, const unsigned short* __restrict__ qvl,
    unsigned short* __restrict__ outHi, unsigned short* __restrict__ outLo)
{
    extern __shared__ unsigned short smem[];

    const int tid = threadIdx.x;
    const int w = tid >> 5, lane = tid & 31;
    const int g = lane >> 2, tig = lane & 3;
    const int lgrp = lane >> 3, lrow = lane & 7;
    const int bh = blockIdx.y, b = bh >> 4, h = bh & 15;
    const int qt = (gridDim.x - 1) - blockIdx.x;   // heavy-first
    const int q0 = qt * 64;

    auto load_kv = [&](int jb, int st) {
        int row = tid >> 1, half = tid & 1;
        size_t gk = ((size_t)(b * Tdim + jb * 64 + row)) * C3 + Cdim + h * Ddim + half * 32;
        size_t gv = gk + Cdim;
        unsigned short* base = smem + st * ABUF + row * APAD + half * 32;
#pragma unroll
        for (int i = 0; i < 4; i++) {
            cp_async16(base + 0 * ATILE + i * 8, qvh + gk + i * 8);
            cp_async16(base + 1 * ATILE + i * 8, qvl + gk + i * 8);
            cp_async16(base + 2 * ATILE + i * 8, qvh + gv + i * 8);
            cp_async16(base + 3 * ATILE + i * 8, qvl + gv + i * 8);
        }
    };

    // Stage Q through stage-1 K buffers
    {
        int row = tid >> 1, half = tid & 1;
        size_t go = ((size_t)(b * Tdim + q0 + row)) * C3 + h * Ddim + half * 32;
        const uint4* gh = reinterpret_cast<const uint4*>(qvh + go);
        const uint4* gl = reinterpret_cast<const uint4*>(qvl + go);
        uint4* dh = reinterpret_cast<uint4*>(smem + ABUF + 0 * ATILE + row * APAD + half * 32);
        uint4* dl = reinterpret_cast<uint4*>(smem + ABUF + 1 * ATILE + row * APAD + half * 32);
#pragma unroll
        for (int i = 0; i < 4; i++) { dh[i] = gh[i]; dl[i] = gl[i]; }
    }
    __syncthreads();

    // Hoist Q fragments
    uint32_t aqh[4][4], aql[4][4];
    {
        const unsigned short* pQh = smem + ABUF;
        const unsigned short* pQl = pQh + ATILE;
        const int ro = w * 16 + (lgrp & 1) * 8 + lrow;
#pragma unroll
        for (int kk = 0; kk < 4; kk++) {
            int co = kk * 16 + (lgrp >> 1) * 8;
            ldmatrix_x4(aqh[kk], smem_u32(pQh + ro * APAD + co));
            ldmatrix_x4(aql[kk], smem_u32(pQl + ro * APAD + co));
        }
    }

    load_kv(0, 0);
    cp_async_commit();

    float m0 = -1e30f, m1 = -1e30f, l0 = 0.0f, l1 = 0.0f;
    float O[8][4];
#pragma unroll
    for (int dt = 0; dt < 8; dt++)
#pragma unroll
        for (int v = 0; v < 4; v++) O[dt][v] = 0.0f;

    const int kb_ro = (lgrp >> 1) * 8 + lrow;
    const int kb_co = (lgrp & 1) * 8;
    const int vt_ro = (lgrp & 1) * 8 + lrow;
    const int vt_co = (lgrp >> 1) * 8;

    for (int jb = 0; jb <= qt; jb++) {
        cp_async_wait<0>();
        __syncthreads();
        if (jb + 1 <= qt) {
            load_kv(jb + 1, (jb + 1) & 1);
            cp_async_commit();
        }

        const unsigned short* pKh = smem + (jb & 1) * ABUF;
        const unsigned short* pKl = pKh + ATILE;
        const unsigned short* pVh = pKl + ATILE;
        const unsigned short* pVl = pVh + ATILE;

        // S = Q K^T (pre-scaled to exp2 domain)
        float S[8][4];
#pragma unroll
        for (int nt = 0; nt < 8; nt++)
#pragma unroll
            for (int v = 0; v < 4; v++) S[nt][v] = 0.0f;
#pragma unroll
        for (int kk = 0; kk < 4; kk++) {
            const int kb = kk * 16;
#pragma unroll
            for (int p = 0; p < 4; p++) {
                uint32_t kh[4], kl[4];
                int off = (p * 16 + kb_ro) * APAD + kb + kb_co;
                ldmatrix_x4(kh, smem_u32(pKh + off));
                ldmatrix_x4(kl, smem_u32(pKl + off));
                mma_bf16(S[2*p],   aqh[kk][0], aqh[kk][1], aqh[kk][2], aqh[kk][3], kh[0], kh[1]);
                mma_bf16(S[2*p+1], aqh[kk][0], aqh[kk][1], aqh[kk][2], aqh[kk][3], kh[2], kh[3]);
                mma_bf16(S[2*p],   aqh[kk][0], aqh[kk][1], aqh[kk][2], aqh[kk][3], kl[0], kl[1]);
                mma_bf16(S[2*p+1], aqh[kk][0], aqh[kk][1], aqh[kk][2], aqh[kk][3], kl[2], kl[3]);
                mma_bf16(S[2*p],   aql[kk][0], aql[kk][1], aql[kk][2], aql[kk][3], kh[0], kh[1]);
                mma_bf16(S[2*p+1], aql[kk][0], aql[kk][1], aql[kk][2], aql[kk][3], kh[2], kh[3]);
            }
        }

        // Causal mask (diagonal tile only)
        if (jb == qt) {
            const int lq0 = w * 16 + g, lq1 = lq0 + 8;
#pragma unroll
            for (int nt = 0; nt < 8; nt++) {
                int lj = nt * 8 + tig * 2;
                if (lj     > lq0) S[nt][0] = -1e30f;
                if (lj + 1 > lq0) S[nt][1] = -1e30f;
                if (lj     > lq1) S[nt][2] = -1e30f;
                if (lj + 1 > lq1) S[nt][3] = -1e30f;
            }
        }

        // Online softmax (exp2 domain)
        float tm0 = -1e30f, tm1 = -1e30f;
#pragma unroll
        for (int nt = 0; nt < 8; nt++) {
            tm0 = fmaxf(tm0, fmaxf(S[nt][0], S[nt][1]));
            tm1 = fmaxf(tm1, fmaxf(S[nt][2], S[nt][3]));
        }
        tm0 = fmaxf(tm0, __shfl_xor_sync(0xffffffffu, tm0, 1));
        tm0 = fmaxf(tm0, __shfl_xor_sync(0xffffffffu, tm0, 2));
        tm1 = fmaxf(tm1, __shfl_xor_sync(0xffffffffu, tm1, 1));
        tm1 = fmaxf(tm1, __shfl_xor_sync(0xffffffffu, tm1, 2));
        float mn0 = fmaxf(m0, tm0), mn1 = fmaxf(m1, tm1);
        float al0 = ex2(m0 - mn0), al1 = ex2(m1 - mn1);
        m0 = mn0; m1 = mn1;
        l0 *= al0; l1 *= al1;
#pragma unroll
        for (int dt = 0; dt < 8; dt++) {
            O[dt][0] *= al0; O[dt][1] *= al0;
            O[dt][2] *= al1; O[dt][3] *= al1;
        }

        // P split via pack-then-bit-unpack; l from unrounded p
        float rs0 = 0.0f, rs1 = 0.0f;
        uint32_t aPh[4][4], aPl[4][4];
#pragma unroll
        for (int nt = 0; nt < 8; nt++) {
            float p0 = ex2(S[nt][0] - m0);
            float p1 = ex2(S[nt][1] - m0);
            float p2 = ex2(S[nt][2] - m1);
            float p3 = ex2(S[nt][3] - m1);
            rs0 += p0 + p1; rs1 += p2 + p3;
            int kk = nt >> 1, hf = (nt & 1) * 2;
            uint32_t h01 = bf16x2_pack(p0, p1);
            uint32_t h23 = bf16x2_pack(p2, p3);
            aPh[kk][hf + 0] = h01;
            aPh[kk][hf + 1] = h23;
            float p0h = __uint_as_float(h01 << 16);
            float p1h = __uint_as_float(h01 & 0xFFFF0000u);
            float p2h = __uint_as_float(h23 << 16);
            float p3h = __uint_as_float(h23 & 0xFFFF0000u);
            aPl[kk][hf + 0] = bf16x2_pack(p0 - p0h, p1 - p1h);
            aPl[kk][hf + 1] = bf16x2_pack(p2 - p2h, p3 - p3h);
        }
        rs0 += __shfl_xor_sync(0xffffffffu, rs0, 1);
        rs0 += __shfl_xor_sync(0xffffffffu, rs0, 2);
        rs1 += __shfl_xor_sync(0xffffffffu, rs1, 1);
        rs1 += __shfl_xor_sync(0xffffffffu, rs1, 2);
        l0 += rs0; l1 += rs1;

        // O += Ph*Vh + Ph*Vl + Pl*Vh
#pragma unroll
        for (int kk = 0; kk < 4; kk++) {
            const int kb = kk * 16;
#pragma unroll
            for (int p = 0; p < 4; p++) {
                uint32_t vh[4], vl[4];
                int off = (kb + vt_ro) * APAD + p * 16 + vt_co;
                ldmatrix_x4_trans(vh, smem_u32(pVh + off));
                ldmatrix_x4_trans(vl, smem_u32(pVl + off));
                mma_bf16(O[2*p],   aPh[kk][0], aPh[kk][1], aPh[kk][2], aPh[kk][3], vh[0], vh[1]);
                mma_bf16(O[2*p+1], aPh[kk][0], aPh[kk][1], aPh[kk][2], aPh[kk][3], vh[2], vh[3]);
                mma_bf16(O[2*p],   aPh[kk][0], aPh[kk][1], aPh[kk][2], aPh[kk][3], vl[0], vl[1]);
                mma_bf16(O[2*p+1], aPh[kk][0], aPh[kk][1], aPh[kk][2], aPh[kk][3], vl[2], vl[3]);
                mma_bf16(O[2*p],   aPl[kk][0], aPl[kk][1], aPl[kk][2], aPl[kk][3], vh[0], vh[1]);
                mma_bf16(O[2*p+1], aPl[kk][0], aPl[kk][1], aPl[kk][2], aPl[kk][3], vh[2], vh[3]);
            }
        }
    }

    // Epilogue: bf16 hi/lo via pack-unpack
    float inv0 = 1.0f / l0, inv1 = 1.0f / l1;
    int r0 = q0 + w * 16 + g, r1 = r0 + 8;
    size_t o0 = ((size_t)(b * Tdim + r0)) * Cdim + h * Ddim;
    size_t o1 = ((size_t)(b * Tdim + r1)) * Cdim + h * Ddim;
#pragma unroll
    for (int dt = 0; dt < 8; dt++) {
        int d = dt * 8 + tig * 2;
        float v00 = O[dt][0] * inv0, v01 = O[dt][1] * inv0;
        float v10 = O[dt][2] * inv1, v11 = O[dt][3] * inv1;
        uint32_t h0 = bf16x2_pack(v00, v01);
        uint32_t h1 = bf16x2_pack(v10, v11);
        float h00 = __uint_as_float(h0 << 16);
        float h01 = __uint_as_float(h0 & 0xFFFF0000u);
        float h10 = __uint_as_float(h1 << 16);
        float h11 = __uint_as_float(h1 & 0xFFFF0000u);
        *reinterpret_cast<uint32_t*>(outHi + o0 + d) = h0;
        *reinterpret_cast<uint32_t*>(outHi + o1 + d) = h1;
        *reinterpret_cast<uint32_t*>(outLo + o0 + d) = bf16x2_pack(v00 - h00, v01 - h01);
        *reinterpret_cast<uint32_t*>(outLo + o1 + d) = bf16x2_pack(v10 - h10, v11 - h11);
    }
}

// ---------------------------------------------------------------------------
extern "C" void kernel_launch(void* const* d_in, const int* in_sizes, int n_in,
                              void* d_out, int out_size)
{
    (void)in_sizes; (void)n_in; (void)out_size;
    const float* x      = (const float*)d_in[0];
    const float* W_attn = (const float*)d_in[1];
    const float* b_attn = (const float*)d_in[2];
    const float* W_proj = (const float*)d_in[3];
    const float* b_proj = (const float*)d_in[4];
    float* out = (float*)d_out;

    unsigned short *x_hi, *x_lo, *Wa_hi, *Wa_lo, *Wp_hi, *Wp_lo, *ah_hi, *ah_lo, *qkv_hi, *qkv_lo;
    cudaGetSymbolAddress((void**)&x_hi, g_x_hi);
    cudaGetSymbolAddress((void**)&x_lo, g_x_lo);
    cudaGetSymbolAddress((void**)&Wa_hi, g_Wa_hi);
    cudaGetSymbolAddress((void**)&Wa_lo, g_Wa_lo);
    cudaGetSymbolAddress((void**)&Wp_hi, g_Wp_hi);
    cudaGetSymbolAddress((void**)&Wp_lo, g_Wp_lo);
    cudaGetSymbolAddress((void**)&ah_hi, g_ah_hi);
    cudaGetSymbolAddress((void**)&ah_lo, g_ah_lo);
    cudaGetSymbolAddress((void**)&qkv_hi, g_qkv_hi);
    cudaGetSymbolAddress((void**)&qkv_lo, g_qkv_lo);

    cudaFuncSetAttribute(gemm_mma_kernel,
                         cudaFuncAttributeMaxDynamicSharedMemorySize, GEMM_SMEM_BYTES);
    cudaFuncSetAttribute(attn_mma_kernel,
                         cudaFuncAttributeMaxDynamicSharedMemorySize, ATTN_SMEM_BYTES);

    // 0) Fused, vectorized input splits
    fused_split_kernel<<<SPLIT_BLOCKS, 256>>>(
        x, x_hi, x_lo, W_attn, Wa_hi, Wa_lo, W_proj, Wp_hi, Wp_lo);
    // 1) QKV = x @ W_attn + b_attn -> bf16 hi/lo; Q columns pre-scaled
    gemm_mma_kernel<<<dim3(C3 / BN, Mrows / BM), 256, GEMM_SMEM_BYTES>>>(
        x_hi, x_lo, Wa_hi, Wa_lo, b_attn, nullptr, qkv_hi, qkv_lo,
        Mrows, C3, Cdim, Cdim, QSCALE);
    // 2) Tensor-core flash attention -> bf16 hi/lo
    attn_mma_kernel<<<dim3(Tdim / 64, Bdim * Hdim), 128, ATTN_SMEM_BYTES>>>(
        qkv_hi, qkv_lo, ah_hi, ah_lo);
    // 3) out = att @ W_proj + b_proj (fp32 epilogue)
    gemm_mma_kernel<<<dim3(Cdim / BN, Mrows / BM), 256, GEMM_SMEM_BYTES>>>(
        ah_hi, ah_lo, Wp_hi, Wp_lo, b_proj, out, nullptr, nullptr,
        Mrows, Cdim, Cdim, 0, 1.0f);
}